// round 1
// baseline (speedup 1.0000x reference)
#include <cuda_runtime.h>
#include <math.h>

#define MP 120000
#define CCH 64
#define G64 1875   // MP / 64 exactly

// ---------------- scratch (static device globals; no runtime allocs) ----------
__device__ float g_A[MP * CCH];
__device__ float g_B[MP * CCH];
__device__ float g_V[MP * CCH];
__device__ float g_ms[4 * MP * CCH];
__device__ float g_sumx[MP * CCH];
__device__ float g_vsum[MP * CCH];
__device__ float g_vcnt[MP];

__device__ __forceinline__ float lrelu(float x, float a) { return x > 0.f ? x : a * x; }

__device__ __forceinline__ void gemm_step(const float* __restrict__ Ws,
                                          const float* __restrict__ As,
                                          int c, int tx, int ty, float acc[4][4]) {
    float4 w4 = *(const float4*)&Ws[c * 68 + tx * 4];
    float a0 = As[(ty * 4 + 0) * 68 + c];
    float a1 = As[(ty * 4 + 1) * 68 + c];
    float a2 = As[(ty * 4 + 2) * 68 + c];
    float a3 = As[(ty * 4 + 3) * 68 + c];
    acc[0][0] += a0 * w4.x; acc[0][1] += a0 * w4.y; acc[0][2] += a0 * w4.z; acc[0][3] += a0 * w4.w;
    acc[1][0] += a1 * w4.x; acc[1][1] += a1 * w4.y; acc[1][2] += a1 * w4.z; acc[1][3] += a1 * w4.w;
    acc[2][0] += a2 * w4.x; acc[2][1] += a2 * w4.y; acc[2][2] += a2 * w4.z; acc[2][3] += a2 * w4.w;
    acc[3][0] += a3 * w4.x; acc[3][1] += a3 * w4.y; acc[3][2] += a3 * w4.z; acc[3][3] += a3 * w4.w;
}

__global__ __launch_bounds__(256) void gemm64_kernel(
    const float* __restrict__ X, const float* __restrict__ W,
    const float* __restrict__ s, const float* __restrict__ b,
    float* __restrict__ out, int mode, const float* __restrict__ feats) {
    __shared__ float Ws[64 * 68];
    __shared__ float Xs[64 * 68];
    const int tid = threadIdx.x;
    const int m0 = blockIdx.x * 64;
#pragma unroll
    for (int j = 0; j < 4; j++) {
        int f = tid + 256 * j;
        int r = f >> 4, c4 = f & 15;
        *(float4*)&Ws[r * 68 + c4 * 4] = ((const float4*)W)[f];
        *(float4*)&Xs[r * 68 + c4 * 4] = *(const float4*)&X[(m0 + r) * 64 + c4 * 4];
    }
    __syncthreads();
    const int tx = tid & 15, ty = tid >> 4;
    float acc[4][4] = {};
#pragma unroll 8
    for (int c = 0; c < 64; c++) gemm_step(Ws, Xs, c, tx, ty, acc);

    float4 sv = *(const float4*)&s[tx * 4];
    float4 bv = *(const float4*)&b[tx * 4];
#pragma unroll
    for (int i = 0; i < 4; i++) {
        int m = m0 + ty * 4 + i;
        float4 o;
        o.x = lrelu(acc[i][0] * sv.x + bv.x, 0.01f);
        o.y = lrelu(acc[i][1] * sv.y + bv.y, 0.01f);
        o.z = lrelu(acc[i][2] * sv.z + bv.z, 0.01f);
        o.w = lrelu(acc[i][3] * sv.w + bv.w, 0.01f);
        if (mode == 1) {
            float4 fr = *(const float4*)&feats[m * 64 + tx * 4];
            o.x = lrelu(o.x + fr.x, 0.1f);
            o.y = lrelu(o.y + fr.y, 0.1f);
            o.z = lrelu(o.z + fr.z, 0.1f);
            o.w = lrelu(o.w + fr.w, 0.1f);
        }
        *(float4*)&out[m * 64 + tx * 4] = o;
    }
}

__global__ __launch_bounds__(256) void conv27_kernel(
    const float* __restrict__ H, const int* __restrict__ nbr,
    const float* __restrict__ W3, const float* __restrict__ s,
    const float* __restrict__ b, float* __restrict__ out) {
    __shared__ float Ws[64 * 68];
    __shared__ float As[64 * 68];
    __shared__ int nidx[64 * 28];
    const int tid = threadIdx.x;
    const int m0 = blockIdx.x * 64;
    for (int f = tid; f < 64 * 27; f += 256) {
        int r = f / 27, k = f % 27;
        nidx[r * 28 + k] = nbr[(m0 + r) * 27 + k];
    }
    __syncthreads();
    const int tx = tid & 15, ty = tid >> 4;
    float acc[4][4] = {};
    for (int k = 0; k < 27; k++) {
#pragma unroll
        for (int j = 0; j < 4; j++) {
            int f = tid + 256 * j;
            int r = f >> 4, c4 = f & 15;
            *(float4*)&Ws[r * 68 + c4 * 4] = ((const float4*)(W3 + k * 4096))[f];
            int row = nidx[r * 28 + k];
            float4 v = make_float4(0.f, 0.f, 0.f, 0.f);
            if (row >= 0) v = *(const float4*)&H[row * 64 + c4 * 4];
            *(float4*)&As[r * 68 + c4 * 4] = v;
        }
        __syncthreads();
#pragma unroll 8
        for (int c = 0; c < 64; c++) gemm_step(Ws, As, c, tx, ty, acc);
        __syncthreads();
    }
    float4 sv = *(const float4*)&s[tx * 4];
    float4 bv = *(const float4*)&b[tx * 4];
#pragma unroll
    for (int i = 0; i < 4; i++) {
        int m = m0 + ty * 4 + i;
        float4 o;
        o.x = lrelu(acc[i][0] * sv.x + bv.x, 0.01f);
        o.y = lrelu(acc[i][1] * sv.y + bv.y, 0.01f);
        o.z = lrelu(acc[i][2] * sv.z + bv.z, 0.01f);
        o.w = lrelu(acc[i][3] * sv.w + bv.w, 0.01f);
        *(float4*)&out[m * 64 + tx * 4] = o;
    }
}

__global__ void zero_kernel(float* __restrict__ vsum, float* __restrict__ vcnt) {
    int gid = blockIdx.x * 256 + threadIdx.x;
    if (gid < MP * 64) vsum[gid] = 0.f;
    if (gid < MP) vcnt[gid] = 0.f;
}

__global__ void scatter_kernel(const float* __restrict__ V, const int* __restrict__ seg,
                               float* __restrict__ vsum, float* __restrict__ vcnt) {
    int gid = blockIdx.x * 256 + threadIdx.x;
    if (gid >= MP * 64) return;
    int m = gid >> 6, c = gid & 63;
    int sg = seg[m];
    atomicAdd(&vsum[sg * 64 + c], V[gid]);
    if (c == 0) atomicAdd(&vcnt[sg], 1.0f);
}

__global__ __launch_bounds__(256) void proj_kernel(
    const float* __restrict__ V, const int* __restrict__ seg,
    const float* __restrict__ vsum, const float* __restrict__ vcnt,
    const float* __restrict__ W, const float* __restrict__ pb,
    const float* __restrict__ ps, const float* __restrict__ pbb,
    float* __restrict__ out) {
    __shared__ float Ws[64 * 68];
    __shared__ float Xs[64 * 68];
    const int tid = threadIdx.x;
    const int m0 = blockIdx.x * 64;
#pragma unroll
    for (int j = 0; j < 4; j++) {
        int f = tid + 256 * j;
        int r = f >> 4, c4 = f & 15;
        *(float4*)&Ws[r * 68 + c4 * 4] = ((const float4*)W)[f];
        int m = m0 + r;
        int sg = seg[m];
        float rc = 1.0f / fmaxf(vcnt[sg], 1.0f);
        float4 v = *(const float4*)&V[m * 64 + c4 * 4];
        float4 su = *(const float4*)&vsum[sg * 64 + c4 * 4];
        float4 os;
        os.x = (v.x - su.x * rc) * v.x;
        os.y = (v.y - su.y * rc) * v.y;
        os.z = (v.z - su.z * rc) * v.z;
        os.w = (v.w - su.w * rc) * v.w;
        *(float4*)&Xs[r * 68 + c4 * 4] = os;
    }
    __syncthreads();
    const int tx = tid & 15, ty = tid >> 4;
    float acc[4][4] = {};
#pragma unroll 8
    for (int c = 0; c < 64; c++) gemm_step(Ws, Xs, c, tx, ty, acc);

    float4 bv = *(const float4*)&pb[tx * 4];
    float4 sv = *(const float4*)&ps[tx * 4];
    float4 b2 = *(const float4*)&pbb[tx * 4];
#pragma unroll
    for (int i = 0; i < 4; i++) {
        int m = m0 + ty * 4 + i;
        float4 o;
        o.x = lrelu((acc[i][0] + bv.x) * sv.x + b2.x, 0.01f);
        o.y = lrelu((acc[i][1] + bv.y) * sv.y + b2.y, 0.01f);
        o.z = lrelu((acc[i][2] + bv.z) * sv.z + b2.z, 0.01f);
        o.w = lrelu((acc[i][3] + bv.w) * sv.w + b2.w, 0.01f);
        *(float4*)&out[m * 64 + tx * 4] = o;
    }
}

__global__ void sumx_kernel(const float* __restrict__ ms, float* __restrict__ sumx) {
    int g = blockIdx.x * 256 + threadIdx.x;
    if (g >= MP * 16) return;
    float4 a = ((const float4*)ms)[g];
    float4 b = ((const float4*)(ms + (size_t)MP * 64))[g];
    float4 c = ((const float4*)(ms + (size_t)2 * MP * 64))[g];
    float4 d = ((const float4*)(ms + (size_t)3 * MP * 64))[g];
    a.x += b.x + c.x + d.x;
    a.y += b.y + c.y + d.y;
    a.z += b.z + c.z + d.z;
    a.w += b.w + c.w + d.w;
    ((float4*)sumx)[g] = a;
}

__global__ __launch_bounds__(256) void attn_kernel(
    const float* __restrict__ sumx, const float* __restrict__ ms,
    const float* __restrict__ aw, const float* __restrict__ ab,
    const float* __restrict__ as_, const float* __restrict__ abb,
    float* __restrict__ fused) {
    __shared__ float Ws[64 * 68];
    __shared__ float Xs[64 * 68];
    const int tid = threadIdx.x;
    const int m0 = blockIdx.x * 64;
#pragma unroll
    for (int j = 0; j < 4; j++) {
        int f = tid + 256 * j;
        int r = f >> 4, c4 = f & 15;
        *(float4*)&Xs[r * 68 + c4 * 4] = *(const float4*)&sumx[(m0 + r) * 64 + c4 * 4];
    }
    const int tx = tid & 15, ty = tid >> 4;
    float fac[4][4] = {};
    for (int i = 0; i < 4; i++) {
#pragma unroll
        for (int j = 0; j < 4; j++) {
            int f = tid + 256 * j;
            int r = f >> 4, c4 = f & 15;
            *(float4*)&Ws[r * 68 + c4 * 4] = ((const float4*)(aw + i * 4096))[f];
        }
        __syncthreads();
        float acc[4][4] = {};
#pragma unroll 8
        for (int c = 0; c < 64; c++) gemm_step(Ws, Xs, c, tx, ty, acc);

        float4 bv = *(const float4*)&ab[i * 64 + tx * 4];
        float4 sv = *(const float4*)&as_[i * 64 + tx * 4];
        float4 b2 = *(const float4*)&abb[i * 64 + tx * 4];
#pragma unroll
        for (int ii = 0; ii < 4; ii++) {
            int m = m0 + ty * 4 + ii;
            float4 mv = *(const float4*)&ms[((size_t)i * MP + m) * 64 + tx * 4];
            float ax = 1.0f / (1.0f + __expf(-((acc[ii][0] + bv.x) * sv.x + b2.x)));
            float ay = 1.0f / (1.0f + __expf(-((acc[ii][1] + bv.y) * sv.y + b2.y)));
            float az = 1.0f / (1.0f + __expf(-((acc[ii][2] + bv.z) * sv.z + b2.z)));
            float aw4 = 1.0f / (1.0f + __expf(-((acc[ii][3] + bv.w) * sv.w + b2.w)));
            fac[ii][0] += ax * mv.x;
            fac[ii][1] += ay * mv.y;
            fac[ii][2] += az * mv.z;
            fac[ii][3] += aw4 * mv.w;
        }
        __syncthreads();
    }
#pragma unroll
    for (int i = 0; i < 4; i++) {
        int m = m0 + ty * 4 + i;
        float4 o = make_float4(fac[i][0], fac[i][1], fac[i][2], fac[i][3]);
        *(float4*)&fused[m * 64 + tx * 4] = o;
    }
}

__global__ __launch_bounds__(256) void gemm_n20_kernel(
    const float* __restrict__ X, const float* __restrict__ W,
    const float* __restrict__ b, float* __restrict__ out) {
    __shared__ float Xs[128 * 68];
    __shared__ float Ws[64 * 20];
    __shared__ float bs[20];
    const int tid = threadIdx.x;
    const int m0 = blockIdx.x * 128;
#pragma unroll
    for (int j = 0; j < 8; j++) {
        int f = tid + 256 * j;
        int r = f >> 4, c4 = f & 15;
        int m = m0 + r;
        float4 v = make_float4(0.f, 0.f, 0.f, 0.f);
        if (m < MP) v = *(const float4*)&X[m * 64 + c4 * 4];
        *(float4*)&Xs[r * 68 + c4 * 4] = v;
    }
    for (int f = tid; f < 64 * 20; f += 256) Ws[f] = W[f];
    if (tid < 20) bs[tid] = b[tid];
    __syncthreads();
    int r = tid >> 1, half = tid & 1, n0 = half * 10;
    int m = m0 + r;
    if (m < MP) {
        float acc[10];
#pragma unroll
        for (int j = 0; j < 10; j++) acc[j] = bs[n0 + j];
#pragma unroll 8
        for (int c = 0; c < 64; c++) {
            float x = Xs[r * 68 + c];
#pragma unroll
            for (int j = 0; j < 10; j++) acc[j] += x * Ws[c * 20 + n0 + j];
        }
#pragma unroll
        for (int j = 0; j < 10; j++) out[m * 20 + n0 + j] = acc[j];
    }
}

extern "C" void kernel_launch(void* const* d_in, const int* in_sizes, int n_in,
                              void* d_out, int out_size) {
    const float* feats   = (const float*)d_in[0];
    const float* w1a     = (const float*)d_in[1];
    const float* s1a     = (const float*)d_in[2];
    const float* b1a     = (const float*)d_in[3];
    const float* w3      = (const float*)d_in[4];
    const float* s3      = (const float*)d_in[5];
    const float* b3      = (const float*)d_in[6];
    const float* w1b     = (const float*)d_in[7];
    const float* s1b     = (const float*)d_in[8];
    const float* b1b     = (const float*)d_in[9];
    const float* aux_w   = (const float*)d_in[10];
    const float* aux_b   = (const float*)d_in[11];
    const float* proj_w  = (const float*)d_in[12];
    const float* proj_b  = (const float*)d_in[13];
    const float* proj_s  = (const float*)d_in[14];
    const float* proj_bb = (const float*)d_in[15];
    const float* attn_w  = (const float*)d_in[16];
    const float* attn_b  = (const float*)d_in[17];
    const float* attn_s  = (const float*)d_in[18];
    const float* attn_bb = (const float*)d_in[19];
    const float* head_w  = (const float*)d_in[20];
    const float* head_b  = (const float*)d_in[21];
    const int*   nbr     = (const int*)d_in[22];
    const int*   inv     = (const int*)d_in[23];

    float* out    = (float*)d_out;
    float* fused  = out;
    float* logits = out + (size_t)MP * 64;
    float* aux    = out + (size_t)MP * 84;

    float *pA, *pB, *pV, *pms, *psx, *pvs, *pvc;
    cudaGetSymbolAddress((void**)&pA, g_A);
    cudaGetSymbolAddress((void**)&pB, g_B);
    cudaGetSymbolAddress((void**)&pV, g_V);
    cudaGetSymbolAddress((void**)&pms, g_ms);
    cudaGetSymbolAddress((void**)&psx, g_sumx);
    cudaGetSymbolAddress((void**)&pvs, g_vsum);
    cudaGetSymbolAddress((void**)&pvc, g_vcnt);

    const float* x = feats;
    for (int i = 0; i < 4; i++) {
        gemm64_kernel<<<G64, 256>>>(x, w1a + i * 4096, s1a + i * 64, b1a + i * 64, pA, 0, nullptr);
        conv27_kernel<<<G64, 256>>>(pA, nbr, w3 + (size_t)i * 27 * 4096, s3 + i * 64, b3 + i * 64, pB);
        if (i < 3) {
            gemm64_kernel<<<G64, 256>>>(pB, w1b + i * 4096, s1b + i * 64, b1b + i * 64, pB, 0, nullptr);
            x = pB;
        } else {
            gemm64_kernel<<<G64, 256>>>(pB, w1b + i * 4096, s1b + i * 64, b1b + i * 64, pV, 1, feats);
        }
    }

    gemm_n20_kernel<<<938, 256>>>(pV, aux_w, aux_b, aux);

    for (int si = 0; si < 4; si++) {
        zero_kernel<<<30000, 256>>>(pvs, pvc);
        scatter_kernel<<<30000, 256>>>(pV, inv + (size_t)si * MP, pvs, pvc);
        proj_kernel<<<G64, 256>>>(pV, inv + (size_t)si * MP, pvs, pvc,
                                  proj_w + si * 4096, proj_b + si * 64,
                                  proj_s + si * 64, proj_bb + si * 64,
                                  pms + (size_t)si * MP * 64);
    }

    sumx_kernel<<<7500, 256>>>(pms, psx);
    attn_kernel<<<G64, 256>>>(psx, pms, attn_w, attn_b, attn_s, attn_bb, fused);
    gemm_n20_kernel<<<938, 256>>>(fused, head_w, head_b, logits);
}

// round 3
// speedup vs baseline: 2.5998x; 2.5998x over previous
#include <cuda_runtime.h>
#include <cuda_fp16.h>
#include <math.h>
#include <stdint.h>

#define MP 120000
#define G64 1875    // MP / 64
#define GTC 938     // ceil(MP / 128)

// ---------------- scratch (static device globals; no runtime allocs) ----------
__device__ float  g_B[MP * 64];
__device__ float  g_V[MP * 64];
__device__ __half g_H16[MP * 64];
__device__ __half g_Wh[4 * 27 * 4096];
__device__ __half g_Wl[4 * 27 * 4096];
__device__ float  g_ms[4 * MP * 64];
__device__ float  g_sumx[MP * 64];
__device__ float  g_vsum[MP * 64];
__device__ float  g_vcnt[MP];

__device__ __forceinline__ float lrelu(float x, float a) { return x > 0.f ? x : a * x; }

__device__ __forceinline__ uint32_t smem_u32(const void* p) {
    uint32_t a;
    asm("{ .reg .u64 t; cvta.to.shared.u64 t, %1; cvt.u32.u64 %0, t; }" : "=r"(a) : "l"(p));
    return a;
}

__device__ __forceinline__ void ldm4(uint32_t r[4], uint32_t addr) {
    asm volatile("ldmatrix.sync.aligned.m8n8.x4.shared.b16 {%0,%1,%2,%3}, [%4];"
                 : "=r"(r[0]), "=r"(r[1]), "=r"(r[2]), "=r"(r[3]) : "r"(addr));
}

__device__ __forceinline__ void mma16816(float c[4], const uint32_t a[4],
                                         uint32_t b0, uint32_t b1) {
    asm volatile(
        "mma.sync.aligned.m16n8k16.row.col.f32.f16.f16.f32 "
        "{%0,%1,%2,%3},{%4,%5,%6,%7},{%8,%9},{%0,%1,%2,%3};"
        : "+f"(c[0]), "+f"(c[1]), "+f"(c[2]), "+f"(c[3])
        : "r"(a[0]), "r"(a[1]), "r"(a[2]), "r"(a[3]), "r"(b0), "r"(b1));
}

#define CP16(dst, src) \
    asm volatile("cp.async.cg.shared.global [%0], [%1], 16;" :: "r"(dst), "l"(src))
#define CP_COMMIT() asm volatile("cp.async.commit_group;" ::: "memory")
#define CP_WAIT(n)  asm volatile("cp.async.wait_group %0;" :: "n"(n) : "memory")

// ================================ FFMA GEMMs ==================================
__device__ __forceinline__ void gemm_step(const float* __restrict__ Ws,
                                          const float* __restrict__ As,
                                          int c, int tx, int ty, float acc[4][4]) {
    float4 w4 = *(const float4*)&Ws[c * 68 + tx * 4];
    float a0 = As[(ty * 4 + 0) * 68 + c];
    float a1 = As[(ty * 4 + 1) * 68 + c];
    float a2 = As[(ty * 4 + 2) * 68 + c];
    float a3 = As[(ty * 4 + 3) * 68 + c];
    acc[0][0] += a0 * w4.x; acc[0][1] += a0 * w4.y; acc[0][2] += a0 * w4.z; acc[0][3] += a0 * w4.w;
    acc[1][0] += a1 * w4.x; acc[1][1] += a1 * w4.y; acc[1][2] += a1 * w4.z; acc[1][3] += a1 * w4.w;
    acc[2][0] += a2 * w4.x; acc[2][1] += a2 * w4.y; acc[2][2] += a2 * w4.z; acc[2][3] += a2 * w4.w;
    acc[3][0] += a3 * w4.x; acc[3][1] += a3 * w4.y; acc[3][2] += a3 * w4.z; acc[3][3] += a3 * w4.w;
}

// mode 0: out float = lrelu01(acc*s+b)
// mode 1: float t = lrelu01(acc*s+b); out = lrelu(t + feats, 0.1)
// mode 2: out half  = lrelu01(acc*s+b)   (feeds conv)
__global__ __launch_bounds__(256) void gemm64_kernel(
    const float* __restrict__ X, const float* __restrict__ W,
    const float* __restrict__ s, const float* __restrict__ b,
    float* __restrict__ outf, __half* __restrict__ outh,
    int mode, const float* __restrict__ feats) {
    __shared__ float Ws[64 * 68];
    __shared__ float Xs[64 * 68];
    const int tid = threadIdx.x;
    const int m0 = blockIdx.x * 64;
#pragma unroll
    for (int j = 0; j < 4; j++) {
        int f = tid + 256 * j;
        int r = f >> 4, c4 = f & 15;
        *(float4*)&Ws[r * 68 + c4 * 4] = ((const float4*)W)[f];
        *(float4*)&Xs[r * 68 + c4 * 4] = *(const float4*)&X[(size_t)(m0 + r) * 64 + c4 * 4];
    }
    __syncthreads();
    const int tx = tid & 15, ty = tid >> 4;
    float acc[4][4] = {};
#pragma unroll 8
    for (int c = 0; c < 64; c++) gemm_step(Ws, Xs, c, tx, ty, acc);

    float4 sv = *(const float4*)&s[tx * 4];
    float4 bv = *(const float4*)&b[tx * 4];
#pragma unroll
    for (int i = 0; i < 4; i++) {
        int m = m0 + ty * 4 + i;
        float4 o;
        o.x = lrelu(acc[i][0] * sv.x + bv.x, 0.01f);
        o.y = lrelu(acc[i][1] * sv.y + bv.y, 0.01f);
        o.z = lrelu(acc[i][2] * sv.z + bv.z, 0.01f);
        o.w = lrelu(acc[i][3] * sv.w + bv.w, 0.01f);
        if (mode == 2) {
            __half2 h0 = __float22half2_rn(make_float2(o.x, o.y));
            __half2 h1 = __float22half2_rn(make_float2(o.z, o.w));
            *(__half2*)&outh[(size_t)m * 64 + tx * 4]     = h0;
            *(__half2*)&outh[(size_t)m * 64 + tx * 4 + 2] = h1;
        } else {
            if (mode == 1) {
                float4 fr = *(const float4*)&feats[(size_t)m * 64 + tx * 4];
                o.x = lrelu(o.x + fr.x, 0.1f);
                o.y = lrelu(o.y + fr.y, 0.1f);
                o.z = lrelu(o.z + fr.z, 0.1f);
                o.w = lrelu(o.w + fr.w, 0.1f);
            }
            *(float4*)&outf[(size_t)m * 64 + tx * 4] = o;
        }
    }
}

// ============ conv weight prep: transpose + scale(32) + fp16 hi/lo split ======
__global__ void wsplit_kernel(const float* __restrict__ W3,
                              __half* __restrict__ Wh, __half* __restrict__ Wl) {
    int g = blockIdx.x * 256 + threadIdx.x;
    if (g >= 4 * 27 * 4096) return;
    int t = g >> 12;
    int rc = g & 4095;
    int d = rc >> 6, c = rc & 63;
    float w = W3[(size_t)t * 4096 + c * 64 + d] * 32.0f;
    __half h = __float2half_rn(w);
    Wh[(size_t)t * 4096 + d * 64 + c] = h;
    Wl[(size_t)t * 4096 + d * 64 + c] = __float2half_rn(w - __half2float(h));
}

// =================== mma.sync fp16 27-tap submanifold conv ====================
// smem: nidxT[27][128] int (13824B pad->14336) | A stages 16KB x2 | Wh/Wl 8KB x4
#define CV_A0   14336
#define CV_A1   30720
#define CV_WH0  47104
#define CV_WL0  55296
#define CV_WH1  63488
#define CV_WL1  71680
#define CV_TOT  79872

__device__ __forceinline__ void cv_fill(uint32_t sb, int stage, int k,
                                        const int* __restrict__ nidxT,
                                        const __half* __restrict__ H,
                                        const __half* __restrict__ Wh,
                                        const __half* __restrict__ Wl, int tid) {
    uint32_t a_s = sb + (stage ? CV_A1 : CV_A0);
    uint32_t h_s = sb + (stage ? CV_WH1 : CV_WH0);
    uint32_t l_s = sb + (stage ? CV_WL1 : CV_WL0);
#pragma unroll
    for (int j = 0; j < 4; j++) {
        int t = tid + j * 256;
        int r = t >> 3, c = t & 7;
        int row = nidxT[k * 128 + r];
        uint32_t dst = a_s + r * 128 + ((c ^ (r & 7)) << 4);
        if (row >= 0) {
            CP16(dst, H + (size_t)row * 64 + c * 8);
        } else {
            uint32_t z = 0;
            asm volatile("st.shared.v4.b32 [%0], {%1,%1,%1,%1};" :: "r"(dst), "r"(z));
        }
    }
    const __half* WhK = Wh + (size_t)k * 4096;
    const __half* WlK = Wl + (size_t)k * 4096;
#pragma unroll
    for (int j = 0; j < 2; j++) {
        int t = tid + j * 256;
        int r = t >> 3, c = t & 7;
        uint32_t off = r * 128 + ((c ^ (r & 7)) << 4);
        CP16(h_s + off, WhK + r * 64 + c * 8);
        CP16(l_s + off, WlK + r * 64 + c * 8);
    }
}

__global__ __launch_bounds__(256, 2) void conv27_mma_kernel(
    const __half* __restrict__ H, const int* __restrict__ nbr,
    const __half* __restrict__ Wh, const __half* __restrict__ Wl,
    const float* __restrict__ s, const float* __restrict__ b,
    float* __restrict__ out) {
    extern __shared__ char smc[];
    const uint32_t sb = smem_u32(smc);
    const int tid = threadIdx.x;
    const int lane = tid & 31, wid = tid >> 5;
    const int m0 = blockIdx.x * 128;
    int* nidxT = (int*)smc;
    for (int t = tid; t < 27 * 128; t += 256) {
        int k = t >> 7, r = t & 127;
        int m = m0 + r;
        nidxT[t] = (m < MP) ? nbr[(size_t)m * 27 + k] : -1;
    }
    __syncthreads();

    cv_fill(sb, 0, 0, nidxT, H, Wh, Wl, tid);
    CP_COMMIT();

    const int wm = (wid >> 1) * 32;
    const int wn = (wid & 1) * 32;
    float acc[2][4][4] = {};

    for (int k = 0; k < 27; k++) {
        int st = k & 1;
        if (k < 26) {
            cv_fill(sb, st ^ 1, k + 1, nidxT, H, Wh, Wl, tid);
            CP_COMMIT();
            CP_WAIT(1);
        } else {
            CP_WAIT(0);
        }
        __syncthreads();
        uint32_t a_s = sb + (st ? CV_A1 : CV_A0);
        uint32_t h_s = sb + (st ? CV_WH1 : CV_WH0);
        uint32_t l_s = sb + (st ? CV_WL1 : CV_WL0);
#pragma unroll
        for (int kb = 0; kb < 4; kb++) {
            uint32_t a[2][4], wh[2][4], wl[2][4];
#pragma unroll
            for (int mt = 0; mt < 2; mt++) {
                int r = wm + mt * 16 + (lane & 15);
                int lc = kb * 2 + (lane >> 4);
                ldm4(a[mt], a_s + r * 128 + ((lc ^ (r & 7)) << 4));
            }
#pragma unroll
            for (int np = 0; np < 2; np++) {
                int r = wn + np * 16 + (lane & 7) + ((lane & 16) ? 8 : 0);
                int lc = kb * 2 + ((lane >> 3) & 1);
                uint32_t off = r * 128 + ((lc ^ (r & 7)) << 4);
                ldm4(wh[np], h_s + off);
                ldm4(wl[np], l_s + off);
            }
#pragma unroll
            for (int mt = 0; mt < 2; mt++)
#pragma unroll
                for (int nt = 0; nt < 4; nt++) {
                    int np = nt >> 1, q = (nt & 1) * 2;
                    mma16816(acc[mt][nt], a[mt], wh[np][q], wh[np][q + 1]);
                    mma16816(acc[mt][nt], a[mt], wl[np][q], wl[np][q + 1]);
                }
        }
        __syncthreads();
    }

    const int qr = lane >> 2, qc = lane & 3;
#pragma unroll
    for (int mt = 0; mt < 2; mt++) {
#pragma unroll
        for (int nt = 0; nt < 4; nt++) {
            int col = wn + nt * 8 + qc * 2;
            float2 s2 = *(const float2*)&s[col];
            float2 b2 = *(const float2*)&b[col];
            s2.x *= 0.03125f; s2.y *= 0.03125f;
            int r0 = m0 + wm + mt * 16 + qr;
            float v0 = lrelu(acc[mt][nt][0] * s2.x + b2.x, 0.01f);
            float v1 = lrelu(acc[mt][nt][1] * s2.y + b2.y, 0.01f);
            if (r0 < MP) *(float2*)&out[(size_t)r0 * 64 + col] = make_float2(v0, v1);
            int r1 = r0 + 8;
            float v2 = lrelu(acc[mt][nt][2] * s2.x + b2.x, 0.01f);
            float v3 = lrelu(acc[mt][nt][3] * s2.y + b2.y, 0.01f);
            if (r1 < MP) *(float2*)&out[(size_t)r1 * 64 + col] = make_float2(v2, v3);
        }
    }
}

// ============================ scatter-mean & misc =============================
__global__ void zero_kernel(float* __restrict__ vsum, float* __restrict__ vcnt) {
    int gid = blockIdx.x * 256 + threadIdx.x;
    if (gid < MP * 64) vsum[gid] = 0.f;
    if (gid < MP) vcnt[gid] = 0.f;
}

__global__ void scatter_kernel(const float* __restrict__ V, const int* __restrict__ seg,
                               float* __restrict__ vsum, float* __restrict__ vcnt) {
    int gid = blockIdx.x * 256 + threadIdx.x;
    if (gid >= MP * 64) return;
    int m = gid >> 6, c = gid & 63;
    int sg = seg[m];
    atomicAdd(&vsum[sg * 64 + c], V[gid]);
    if (c == 0) atomicAdd(&vcnt[sg], 1.0f);
}

__global__ __launch_bounds__(256) void proj_kernel(
    const float* __restrict__ V, const int* __restrict__ seg,
    const float* __restrict__ vsum, const float* __restrict__ vcnt,
    const float* __restrict__ W, const float* __restrict__ pb,
    const float* __restrict__ ps, const float* __restrict__ pbb,
    float* __restrict__ out) {
    __shared__ float Ws[64 * 68];
    __shared__ float Xs[64 * 68];
    const int tid = threadIdx.x;
    const int m0 = blockIdx.x * 64;
#pragma unroll
    for (int j = 0; j < 4; j++) {
        int f = tid + 256 * j;
        int r = f >> 4, c4 = f & 15;
        *(float4*)&Ws[r * 68 + c4 * 4] = ((const float4*)W)[f];
        int m = m0 + r;
        int sg = seg[m];
        float rc = 1.0f / fmaxf(vcnt[sg], 1.0f);
        float4 v = *(const float4*)&V[(size_t)m * 64 + c4 * 4];
        float4 su = *(const float4*)&vsum[(size_t)sg * 64 + c4 * 4];
        float4 os;
        os.x = (v.x - su.x * rc) * v.x;
        os.y = (v.y - su.y * rc) * v.y;
        os.z = (v.z - su.z * rc) * v.z;
        os.w = (v.w - su.w * rc) * v.w;
        *(float4*)&Xs[r * 68 + c4 * 4] = os;
    }
    __syncthreads();
    const int tx = tid & 15, ty = tid >> 4;
    float acc[4][4] = {};
#pragma unroll 8
    for (int c = 0; c < 64; c++) gemm_step(Ws, Xs, c, tx, ty, acc);

    float4 bv = *(const float4*)&pb[tx * 4];
    float4 sv = *(const float4*)&ps[tx * 4];
    float4 b2 = *(const float4*)&pbb[tx * 4];
#pragma unroll
    for (int i = 0; i < 4; i++) {
        int m = m0 + ty * 4 + i;
        float4 o;
        o.x = lrelu((acc[i][0] + bv.x) * sv.x + b2.x, 0.01f);
        o.y = lrelu((acc[i][1] + bv.y) * sv.y + b2.y, 0.01f);
        o.z = lrelu((acc[i][2] + bv.z) * sv.z + b2.z, 0.01f);
        o.w = lrelu((acc[i][3] + bv.w) * sv.w + b2.w, 0.01f);
        *(float4*)&out[(size_t)m * 64 + tx * 4] = o;
    }
}

__global__ void sumx_kernel(const float* __restrict__ ms, float* __restrict__ sumx) {
    int g = blockIdx.x * 256 + threadIdx.x;
    if (g >= MP * 16) return;
    float4 a = ((const float4*)ms)[g];
    float4 b = ((const float4*)(ms + (size_t)MP * 64))[g];
    float4 c = ((const float4*)(ms + (size_t)2 * MP * 64))[g];
    float4 d = ((const float4*)(ms + (size_t)3 * MP * 64))[g];
    a.x += b.x + c.x + d.x;
    a.y += b.y + c.y + d.y;
    a.z += b.z + c.z + d.z;
    a.w += b.w + c.w + d.w;
    ((float4*)sumx)[g] = a;
}

__global__ __launch_bounds__(256) void attn_kernel(
    const float* __restrict__ sumx, const float* __restrict__ ms,
    const float* __restrict__ aw, const float* __restrict__ ab,
    const float* __restrict__ as_, const float* __restrict__ abb,
    float* __restrict__ fused) {
    __shared__ float Ws[64 * 68];
    __shared__ float Xs[64 * 68];
    const int tid = threadIdx.x;
    const int m0 = blockIdx.x * 64;
#pragma unroll
    for (int j = 0; j < 4; j++) {
        int f = tid + 256 * j;
        int r = f >> 4, c4 = f & 15;
        *(float4*)&Xs[r * 68 + c4 * 4] = *(const float4*)&sumx[(size_t)(m0 + r) * 64 + c4 * 4];
    }
    const int tx = tid & 15, ty = tid >> 4;
    float fac[4][4] = {};
    for (int i = 0; i < 4; i++) {
#pragma unroll
        for (int j = 0; j < 4; j++) {
            int f = tid + 256 * j;
            int r = f >> 4, c4 = f & 15;
            *(float4*)&Ws[r * 68 + c4 * 4] = ((const float4*)(aw + i * 4096))[f];
        }
        __syncthreads();
        float acc[4][4] = {};
#pragma unroll 8
        for (int c = 0; c < 64; c++) gemm_step(Ws, Xs, c, tx, ty, acc);

        float4 bv = *(const float4*)&ab[i * 64 + tx * 4];
        float4 sv = *(const float4*)&as_[i * 64 + tx * 4];
        float4 b2 = *(const float4*)&abb[i * 64 + tx * 4];
#pragma unroll
        for (int ii = 0; ii < 4; ii++) {
            int m = m0 + ty * 4 + ii;
            float4 mv = *(const float4*)&ms[((size_t)i * MP + m) * 64 + tx * 4];
            float ax = 1.0f / (1.0f + __expf(-((acc[ii][0] + bv.x) * sv.x + b2.x)));
            float ay = 1.0f / (1.0f + __expf(-((acc[ii][1] + bv.y) * sv.y + b2.y)));
            float az = 1.0f / (1.0f + __expf(-((acc[ii][2] + bv.z) * sv.z + b2.z)));
            float aw4 = 1.0f / (1.0f + __expf(-((acc[ii][3] + bv.w) * sv.w + b2.w)));
            fac[ii][0] += ax * mv.x;
            fac[ii][1] += ay * mv.y;
            fac[ii][2] += az * mv.z;
            fac[ii][3] += aw4 * mv.w;
        }
        __syncthreads();
    }
#pragma unroll
    for (int i = 0; i < 4; i++) {
        int m = m0 + ty * 4 + i;
        float4 o = make_float4(fac[i][0], fac[i][1], fac[i][2], fac[i][3]);
        *(float4*)&fused[(size_t)m * 64 + tx * 4] = o;
    }
}

__global__ __launch_bounds__(256) void gemm_n20_kernel(
    const float* __restrict__ X, const float* __restrict__ W,
    const float* __restrict__ b, float* __restrict__ out) {
    __shared__ float Xs[128 * 68];
    __shared__ float Ws[64 * 20];
    __shared__ float bs[20];
    const int tid = threadIdx.x;
    const int m0 = blockIdx.x * 128;
#pragma unroll
    for (int j = 0; j < 8; j++) {
        int f = tid + 256 * j;
        int r = f >> 4, c4 = f & 15;
        int m = m0 + r;
        float4 v = make_float4(0.f, 0.f, 0.f, 0.f);
        if (m < MP) v = *(const float4*)&X[(size_t)m * 64 + c4 * 4];
        *(float4*)&Xs[r * 68 + c4 * 4] = v;
    }
    for (int f = tid; f < 64 * 20; f += 256) Ws[f] = W[f];
    if (tid < 20) bs[tid] = b[tid];
    __syncthreads();
    int r = tid >> 1, half = tid & 1, n0 = half * 10;
    int m = m0 + r;
    if (m < MP) {
        float acc[10];
#pragma unroll
        for (int j = 0; j < 10; j++) acc[j] = bs[n0 + j];
#pragma unroll 8
        for (int c = 0; c < 64; c++) {
            float x = Xs[r * 68 + c];
#pragma unroll
            for (int j = 0; j < 10; j++) acc[j] += x * Ws[c * 20 + n0 + j];
        }
#pragma unroll
        for (int j = 0; j < 10; j++) out[(size_t)m * 20 + n0 + j] = acc[j];
    }
}

// ==============================================================================
extern "C" void kernel_launch(void* const* d_in, const int* in_sizes, int n_in,
                              void* d_out, int out_size) {
    const float* feats   = (const float*)d_in[0];
    const float* w1a     = (const float*)d_in[1];
    const float* s1a     = (const float*)d_in[2];
    const float* b1a     = (const float*)d_in[3];
    const float* w3      = (const float*)d_in[4];
    const float* s3      = (const float*)d_in[5];
    const float* b3      = (const float*)d_in[6];
    const float* w1b     = (const float*)d_in[7];
    const float* s1b     = (const float*)d_in[8];
    const float* b1b     = (const float*)d_in[9];
    const float* aux_w   = (const float*)d_in[10];
    const float* aux_b   = (const float*)d_in[11];
    const float* proj_w  = (const float*)d_in[12];
    const float* proj_b  = (const float*)d_in[13];
    const float* proj_s  = (const float*)d_in[14];
    const float* proj_bb = (const float*)d_in[15];
    const float* attn_w  = (const float*)d_in[16];
    const float* attn_b  = (const float*)d_in[17];
    const float* attn_s  = (const float*)d_in[18];
    const float* attn_bb = (const float*)d_in[19];
    const float* head_w  = (const float*)d_in[20];
    const float* head_b  = (const float*)d_in[21];
    const int*   nbr     = (const int*)d_in[22];
    const int*   inv     = (const int*)d_in[23];

    float* out    = (float*)d_out;
    float* fused  = out;
    float* logits = out + (size_t)MP * 64;
    float* aux    = out + (size_t)MP * 84;

    float *pB, *pV, *pms, *psx, *pvs, *pvc;
    __half *pH, *pWh, *pWl;
    cudaGetSymbolAddress((void**)&pB, g_B);
    cudaGetSymbolAddress((void**)&pV, g_V);
    cudaGetSymbolAddress((void**)&pms, g_ms);
    cudaGetSymbolAddress((void**)&psx, g_sumx);
    cudaGetSymbolAddress((void**)&pvs, g_vsum);
    cudaGetSymbolAddress((void**)&pvc, g_vcnt);
    cudaGetSymbolAddress((void**)&pH, g_H16);
    cudaGetSymbolAddress((void**)&pWh, g_Wh);
    cudaGetSymbolAddress((void**)&pWl, g_Wl);

    cudaFuncSetAttribute(conv27_mma_kernel, cudaFuncAttributeMaxDynamicSharedMemorySize, CV_TOT);

    wsplit_kernel<<<1728, 256>>>(w3, pWh, pWl);

    const float* x = feats;
    for (int i = 0; i < 4; i++) {
        gemm64_kernel<<<G64, 256>>>(x, w1a + i * 4096, s1a + i * 64, b1a + i * 64,
                                    nullptr, pH, 2, nullptr);
        conv27_mma_kernel<<<GTC, 256, CV_TOT>>>(pH, nbr,
                                                pWh + (size_t)i * 27 * 4096,
                                                pWl + (size_t)i * 27 * 4096,
                                                s3 + i * 64, b3 + i * 64, pB);
        if (i < 3) {
            gemm64_kernel<<<G64, 256>>>(pB, w1b + i * 4096, s1b + i * 64, b1b + i * 64,
                                        pB, nullptr, 0, nullptr);
            x = pB;
        } else {
            gemm64_kernel<<<G64, 256>>>(pB, w1b + i * 4096, s1b + i * 64, b1b + i * 64,
                                        pV, nullptr, 1, feats);
        }
    }

    gemm_n20_kernel<<<938, 256>>>(pV, aux_w, aux_b, aux);

    for (int si = 0; si < 4; si++) {
        zero_kernel<<<30000, 256>>>(pvs, pvc);
        scatter_kernel<<<30000, 256>>>(pV, inv + (size_t)si * MP, pvs, pvc);
        proj_kernel<<<G64, 256>>>(pV, inv + (size_t)si * MP, pvs, pvc,
                                  proj_w + si * 4096, proj_b + si * 64,
                                  proj_s + si * 64, proj_bb + si * 64,
                                  pms + (size_t)si * MP * 64);
    }

    sumx_kernel<<<7500, 256>>>(pms, psx);
    attn_kernel<<<G64, 256>>>(psx, pms, attn_w, attn_b, attn_s, attn_bb, fused);
    gemm_n20_kernel<<<938, 256>>>(fused, head_w, head_b, logits);
}

// round 4
// speedup vs baseline: 3.3355x; 1.2830x over previous
#include <cuda_runtime.h>
#include <cuda_fp16.h>
#include <math.h>
#include <stdint.h>

#define MP 120000
#define G64 1875    // MP / 64
#define GTC 938     // ceil(MP / 128)

// ---------------- scratch (static device globals; no runtime allocs) ----------
__device__ float  g_V[MP * 64];
__device__ __half g_X16[MP * 64];
__device__ __half g_H16[MP * 64];
__device__ __half g_B16[MP * 64];
__device__ __half g_W1a16[4 * 4096];
__device__ __half g_W1b16[4 * 4096];
__device__ __half g_W316[4 * 27 * 4096];
__device__ float  g_ms[4 * MP * 64];
__device__ float  g_sumx[MP * 64];
__device__ float  g_vsum[MP * 64];
__device__ float  g_vcnt[MP];

__device__ __forceinline__ float lrelu(float x, float a) { return x > 0.f ? x : a * x; }

__device__ __forceinline__ uint32_t smem_u32(const void* p) {
    uint32_t a;
    asm("{ .reg .u64 t; cvta.to.shared.u64 t, %1; cvt.u32.u64 %0, t; }" : "=r"(a) : "l"(p));
    return a;
}

__device__ __forceinline__ void ldm4(uint32_t r[4], uint32_t addr) {
    asm volatile("ldmatrix.sync.aligned.m8n8.x4.shared.b16 {%0,%1,%2,%3}, [%4];"
                 : "=r"(r[0]), "=r"(r[1]), "=r"(r[2]), "=r"(r[3]) : "r"(addr));
}

__device__ __forceinline__ void mma16816(float c[4], const uint32_t a[4],
                                         uint32_t b0, uint32_t b1) {
    asm volatile(
        "mma.sync.aligned.m16n8k16.row.col.f32.f16.f16.f32 "
        "{%0,%1,%2,%3},{%4,%5,%6,%7},{%8,%9},{%0,%1,%2,%3};"
        : "+f"(c[0]), "+f"(c[1]), "+f"(c[2]), "+f"(c[3])
        : "r"(a[0]), "r"(a[1]), "r"(a[2]), "r"(a[3]), "r"(b0), "r"(b1));
}

#define CP16(dst, src) \
    asm volatile("cp.async.cg.shared.global [%0], [%1], 16;" :: "r"(dst), "l"(src))
#define CP_COMMIT() asm volatile("cp.async.commit_group;" ::: "memory")
#define CP_WAIT(n)  asm volatile("cp.async.wait_group %0;" :: "n"(n) : "memory")

// =================== weight prep: transpose + fp16 (w1a|w1b|w3) ===============
__global__ void wprep_kernel(const float* __restrict__ w1a, const float* __restrict__ w1b,
                             const float* __restrict__ w3,
                             __half* __restrict__ o1a, __half* __restrict__ o1b,
                             __half* __restrict__ o3) {
    int g = blockIdx.x * 256 + threadIdx.x;
    if (g >= 116 * 4096) return;
    int t = g >> 12;
    int rc = g & 4095;
    int d = rc >> 6, c = rc & 63;
    if (t < 4) {
        o1a[(size_t)t * 4096 + d * 64 + c] = __float2half_rn(w1a[(size_t)t * 4096 + c * 64 + d]);
    } else if (t < 8) {
        int tt = t - 4;
        o1b[(size_t)tt * 4096 + d * 64 + c] = __float2half_rn(w1b[(size_t)tt * 4096 + c * 64 + d]);
    } else {
        int tt = t - 8;
        o3[(size_t)tt * 4096 + d * 64 + c] = __float2half_rn(w3[(size_t)tt * 4096 + c * 64 + d]);
    }
}

__global__ void cvt16_kernel(const float* __restrict__ x, __half* __restrict__ o) {
    int g = blockIdx.x * 256 + threadIdx.x;
    if (g >= MP * 32) return;
    float2 v = ((const float2*)x)[g];
    ((__half2*)o)[g] = __float22half2_rn(v);
}

// ================= tensorized 64x64 GEMM (M-tile 128, 8 warps) ================
// mode 2: outh = half(lrelu01(acc*s+b))
// mode 1: t = lrelu01(acc*s+b); outf = lrelu(t + feats, 0.1)  (fp32)
__global__ __launch_bounds__(256) void gemm64h_kernel(
    const __half* __restrict__ X, const __half* __restrict__ W,
    const float* __restrict__ s, const float* __restrict__ b,
    __half* __restrict__ outh, float* __restrict__ outf,
    int mode, const float* __restrict__ feats) {
    __shared__ __align__(16) char smA[16384];
    __shared__ __align__(16) char smW[8192];
    const uint32_t a_s = smem_u32(smA);
    const uint32_t w_s = smem_u32(smW);
    const int tid = threadIdx.x;
    const int lane = tid & 31, wid = tid >> 5;
    const int m0 = blockIdx.x * 128;

#pragma unroll
    for (int j = 0; j < 4; j++) {
        int f = tid + j * 256;
        int r = f >> 3, c = f & 7;
        uint32_t dst = a_s + r * 128 + ((c ^ (r & 7)) << 4);
        if (m0 + r < MP) {
            CP16(dst, X + (size_t)(m0 + r) * 64 + c * 8);
        } else {
            uint32_t z = 0;
            asm volatile("st.shared.v4.b32 [%0], {%1,%1,%1,%1};" :: "r"(dst), "r"(z));
        }
    }
#pragma unroll
    for (int j = 0; j < 2; j++) {
        int f = tid + j * 256;
        int r = f >> 3, c = f & 7;
        CP16(w_s + r * 128 + ((c ^ (r & 7)) << 4), W + (size_t)r * 64 + c * 8);
    }
    CP_COMMIT();
    CP_WAIT(0);
    __syncthreads();

    const int wm = (wid >> 1) * 32;
    const int wn = (wid & 1) * 32;
    float acc[2][4][4] = {};
#pragma unroll
    for (int kb = 0; kb < 4; kb++) {
        uint32_t a[2][4], wh[2][4];
#pragma unroll
        for (int mt = 0; mt < 2; mt++) {
            int r = wm + mt * 16 + (lane & 15);
            int lc = kb * 2 + (lane >> 4);
            ldm4(a[mt], a_s + r * 128 + ((lc ^ (r & 7)) << 4));
        }
#pragma unroll
        for (int np = 0; np < 2; np++) {
            int r = wn + np * 16 + (lane & 7) + ((lane & 16) ? 8 : 0);
            int lc = kb * 2 + ((lane >> 3) & 1);
            ldm4(wh[np], w_s + r * 128 + ((lc ^ (r & 7)) << 4));
        }
#pragma unroll
        for (int mt = 0; mt < 2; mt++)
#pragma unroll
            for (int nt = 0; nt < 4; nt++) {
                int np = nt >> 1, q = (nt & 1) * 2;
                mma16816(acc[mt][nt], a[mt], wh[np][q], wh[np][q + 1]);
            }
    }

    const int qr = lane >> 2, qc = lane & 3;
#pragma unroll
    for (int mt = 0; mt < 2; mt++) {
#pragma unroll
        for (int nt = 0; nt < 4; nt++) {
            int col = wn + nt * 8 + qc * 2;
            float2 s2 = *(const float2*)&s[col];
            float2 b2 = *(const float2*)&b[col];
            int r0 = m0 + wm + mt * 16 + qr;
            int r1 = r0 + 8;
            float v0 = lrelu(acc[mt][nt][0] * s2.x + b2.x, 0.01f);
            float v1 = lrelu(acc[mt][nt][1] * s2.y + b2.y, 0.01f);
            float v2 = lrelu(acc[mt][nt][2] * s2.x + b2.x, 0.01f);
            float v3 = lrelu(acc[mt][nt][3] * s2.y + b2.y, 0.01f);
            if (mode == 2) {
                if (r0 < MP) *(__half2*)&outh[(size_t)r0 * 64 + col] =
                    __float22half2_rn(make_float2(v0, v1));
                if (r1 < MP) *(__half2*)&outh[(size_t)r1 * 64 + col] =
                    __float22half2_rn(make_float2(v2, v3));
            } else {
                if (r0 < MP) {
                    float2 fr = *(const float2*)&feats[(size_t)r0 * 64 + col];
                    *(float2*)&outf[(size_t)r0 * 64 + col] =
                        make_float2(lrelu(v0 + fr.x, 0.1f), lrelu(v1 + fr.y, 0.1f));
                }
                if (r1 < MP) {
                    float2 fr = *(const float2*)&feats[(size_t)r1 * 64 + col];
                    *(float2*)&outf[(size_t)r1 * 64 + col] =
                        make_float2(lrelu(v2 + fr.x, 0.1f), lrelu(v3 + fr.y, 0.1f));
                }
            }
        }
    }
}

// =================== mma.sync fp16 27-tap submanifold conv ====================
// smem: nidxT[27][128] int (13824 -> 14336) | A stages 16KB x2 | W 8KB x2
#define CV_A0   14336
#define CV_A1   30720
#define CV_WH0  47104
#define CV_WH1  55296
#define CV_TOT  63488

__device__ __forceinline__ void cv_fill(uint32_t sb, int stage, int k,
                                        const int* __restrict__ nidxT,
                                        const __half* __restrict__ H,
                                        const __half* __restrict__ Wh, int tid) {
    uint32_t a_s = sb + (stage ? CV_A1 : CV_A0);
    uint32_t h_s = sb + (stage ? CV_WH1 : CV_WH0);
#pragma unroll
    for (int j = 0; j < 4; j++) {
        int t = tid + j * 256;
        int r = t >> 3, c = t & 7;
        int row = nidxT[k * 128 + r];
        uint32_t dst = a_s + r * 128 + ((c ^ (r & 7)) << 4);
        if (row >= 0) {
            CP16(dst, H + (size_t)row * 64 + c * 8);
        } else {
            uint32_t z = 0;
            asm volatile("st.shared.v4.b32 [%0], {%1,%1,%1,%1};" :: "r"(dst), "r"(z));
        }
    }
    const __half* WhK = Wh + (size_t)k * 4096;
#pragma unroll
    for (int j = 0; j < 2; j++) {
        int t = tid + j * 256;
        int r = t >> 3, c = t & 7;
        CP16(h_s + r * 128 + ((c ^ (r & 7)) << 4), WhK + r * 64 + c * 8);
    }
}

__global__ __launch_bounds__(256, 2) void conv27_mma_kernel(
    const __half* __restrict__ H, const int* __restrict__ nbr,
    const __half* __restrict__ Wh,
    const float* __restrict__ s, const float* __restrict__ b,
    __half* __restrict__ out) {
    extern __shared__ char smc[];
    const uint32_t sb = smem_u32(smc);
    const int tid = threadIdx.x;
    const int lane = tid & 31, wid = tid >> 5;
    const int m0 = blockIdx.x * 128;
    int* nidxT = (int*)smc;
    for (int t = tid; t < 27 * 128; t += 256) {
        int k = t >> 7, r = t & 127;
        int m = m0 + r;
        nidxT[t] = (m < MP) ? nbr[(size_t)m * 27 + k] : -1;
    }
    __syncthreads();

    cv_fill(sb, 0, 0, nidxT, H, Wh, tid);
    CP_COMMIT();

    const int wm = (wid >> 1) * 32;
    const int wn = (wid & 1) * 32;
    float acc[2][4][4] = {};

    for (int k = 0; k < 27; k++) {
        int st = k & 1;
        if (k < 26) {
            cv_fill(sb, st ^ 1, k + 1, nidxT, H, Wh, tid);
            CP_COMMIT();
            CP_WAIT(1);
        } else {
            CP_WAIT(0);
        }
        __syncthreads();
        uint32_t a_s = sb + (st ? CV_A1 : CV_A0);
        uint32_t h_s = sb + (st ? CV_WH1 : CV_WH0);
#pragma unroll
        for (int kb = 0; kb < 4; kb++) {
            uint32_t a[2][4], wh[2][4];
#pragma unroll
            for (int mt = 0; mt < 2; mt++) {
                int r = wm + mt * 16 + (lane & 15);
                int lc = kb * 2 + (lane >> 4);
                ldm4(a[mt], a_s + r * 128 + ((lc ^ (r & 7)) << 4));
            }
#pragma unroll
            for (int np = 0; np < 2; np++) {
                int r = wn + np * 16 + (lane & 7) + ((lane & 16) ? 8 : 0);
                int lc = kb * 2 + ((lane >> 3) & 1);
                ldm4(wh[np], h_s + r * 128 + ((lc ^ (r & 7)) << 4));
            }
#pragma unroll
            for (int mt = 0; mt < 2; mt++)
#pragma unroll
                for (int nt = 0; nt < 4; nt++) {
                    int np = nt >> 1, q = (nt & 1) * 2;
                    mma16816(acc[mt][nt], a[mt], wh[np][q], wh[np][q + 1]);
                }
        }
        __syncthreads();
    }

    const int qr = lane >> 2, qc = lane & 3;
#pragma unroll
    for (int mt = 0; mt < 2; mt++) {
#pragma unroll
        for (int nt = 0; nt < 4; nt++) {
            int col = wn + nt * 8 + qc * 2;
            float2 s2 = *(const float2*)&s[col];
            float2 b2 = *(const float2*)&b[col];
            int r0 = m0 + wm + mt * 16 + qr;
            int r1 = r0 + 8;
            float v0 = lrelu(acc[mt][nt][0] * s2.x + b2.x, 0.01f);
            float v1 = lrelu(acc[mt][nt][1] * s2.y + b2.y, 0.01f);
            float v2 = lrelu(acc[mt][nt][2] * s2.x + b2.x, 0.01f);
            float v3 = lrelu(acc[mt][nt][3] * s2.y + b2.y, 0.01f);
            if (r0 < MP) *(__half2*)&out[(size_t)r0 * 64 + col] =
                __float22half2_rn(make_float2(v0, v1));
            if (r1 < MP) *(__half2*)&out[(size_t)r1 * 64 + col] =
                __float22half2_rn(make_float2(v2, v3));
        }
    }
}

// ============================ scatter-mean & misc =============================
__device__ __forceinline__ void gemm_step(const float* __restrict__ Ws,
                                          const float* __restrict__ As,
                                          int c, int tx, int ty, float acc[4][4]) {
    float4 w4 = *(const float4*)&Ws[c * 68 + tx * 4];
    float a0 = As[(ty * 4 + 0) * 68 + c];
    float a1 = As[(ty * 4 + 1) * 68 + c];
    float a2 = As[(ty * 4 + 2) * 68 + c];
    float a3 = As[(ty * 4 + 3) * 68 + c];
    acc[0][0] += a0 * w4.x; acc[0][1] += a0 * w4.y; acc[0][2] += a0 * w4.z; acc[0][3] += a0 * w4.w;
    acc[1][0] += a1 * w4.x; acc[1][1] += a1 * w4.y; acc[1][2] += a1 * w4.z; acc[1][3] += a1 * w4.w;
    acc[2][0] += a2 * w4.x; acc[2][1] += a2 * w4.y; acc[2][2] += a2 * w4.z; acc[2][3] += a2 * w4.w;
    acc[3][0] += a3 * w4.x; acc[3][1] += a3 * w4.y; acc[3][2] += a3 * w4.z; acc[3][3] += a3 * w4.w;
}

__global__ void zero_kernel(float* __restrict__ vsum, float* __restrict__ vcnt) {
    int gid = blockIdx.x * 256 + threadIdx.x;
    if (gid < MP * 64) vsum[gid] = 0.f;
    if (gid < MP) vcnt[gid] = 0.f;
}

__global__ void scatter_kernel(const float* __restrict__ V, const int* __restrict__ seg,
                               float* __restrict__ vsum, float* __restrict__ vcnt) {
    int gid = blockIdx.x * 256 + threadIdx.x;
    if (gid >= MP * 64) return;
    int m = gid >> 6, c = gid & 63;
    int sg = seg[m];
    atomicAdd(&vsum[sg * 64 + c], V[gid]);
    if (c == 0) atomicAdd(&vcnt[sg], 1.0f);
}

__global__ __launch_bounds__(256) void proj_kernel(
    const float* __restrict__ V, const int* __restrict__ seg,
    const float* __restrict__ vsum, const float* __restrict__ vcnt,
    const float* __restrict__ W, const float* __restrict__ pb,
    const float* __restrict__ ps, const float* __restrict__ pbb,
    float* __restrict__ out) {
    __shared__ float Ws[64 * 68];
    __shared__ float Xs[64 * 68];
    const int tid = threadIdx.x;
    const int m0 = blockIdx.x * 64;
#pragma unroll
    for (int j = 0; j < 4; j++) {
        int f = tid + 256 * j;
        int r = f >> 4, c4 = f & 15;
        *(float4*)&Ws[r * 68 + c4 * 4] = ((const float4*)W)[f];
        int m = m0 + r;
        int sg = seg[m];
        float rc = 1.0f / fmaxf(vcnt[sg], 1.0f);
        float4 v = *(const float4*)&V[(size_t)m * 64 + c4 * 4];
        float4 su = *(const float4*)&vsum[(size_t)sg * 64 + c4 * 4];
        float4 os;
        os.x = (v.x - su.x * rc) * v.x;
        os.y = (v.y - su.y * rc) * v.y;
        os.z = (v.z - su.z * rc) * v.z;
        os.w = (v.w - su.w * rc) * v.w;
        *(float4*)&Xs[r * 68 + c4 * 4] = os;
    }
    __syncthreads();
    const int tx = tid & 15, ty = tid >> 4;
    float acc[4][4] = {};
#pragma unroll 8
    for (int c = 0; c < 64; c++) gemm_step(Ws, Xs, c, tx, ty, acc);

    float4 bv = *(const float4*)&pb[tx * 4];
    float4 sv = *(const float4*)&ps[tx * 4];
    float4 b2 = *(const float4*)&pbb[tx * 4];
#pragma unroll
    for (int i = 0; i < 4; i++) {
        int m = m0 + ty * 4 + i;
        float4 o;
        o.x = lrelu((acc[i][0] + bv.x) * sv.x + b2.x, 0.01f);
        o.y = lrelu((acc[i][1] + bv.y) * sv.y + b2.y, 0.01f);
        o.z = lrelu((acc[i][2] + bv.z) * sv.z + b2.z, 0.01f);
        o.w = lrelu((acc[i][3] + bv.w) * sv.w + b2.w, 0.01f);
        *(float4*)&out[(size_t)m * 64 + tx * 4] = o;
    }
}

__global__ void sumx_kernel(const float* __restrict__ ms, float* __restrict__ sumx) {
    int g = blockIdx.x * 256 + threadIdx.x;
    if (g >= MP * 16) return;
    float4 a = ((const float4*)ms)[g];
    float4 b = ((const float4*)(ms + (size_t)MP * 64))[g];
    float4 c = ((const float4*)(ms + (size_t)2 * MP * 64))[g];
    float4 d = ((const float4*)(ms + (size_t)3 * MP * 64))[g];
    a.x += b.x + c.x + d.x;
    a.y += b.y + c.y + d.y;
    a.z += b.z + c.z + d.z;
    a.w += b.w + c.w + d.w;
    ((float4*)sumx)[g] = a;
}

__global__ __launch_bounds__(256) void attn_kernel(
    const float* __restrict__ sumx, const float* __restrict__ ms,
    const float* __restrict__ aw, const float* __restrict__ ab,
    const float* __restrict__ as_, const float* __restrict__ abb,
    float* __restrict__ fused) {
    __shared__ float Ws[64 * 68];
    __shared__ float Xs[64 * 68];
    const int tid = threadIdx.x;
    const int m0 = blockIdx.x * 64;
#pragma unroll
    for (int j = 0; j < 4; j++) {
        int f = tid + 256 * j;
        int r = f >> 4, c4 = f & 15;
        *(float4*)&Xs[r * 68 + c4 * 4] = *(const float4*)&sumx[(size_t)(m0 + r) * 64 + c4 * 4];
    }
    const int tx = tid & 15, ty = tid >> 4;
    float fac[4][4] = {};
    for (int i = 0; i < 4; i++) {
#pragma unroll
        for (int j = 0; j < 4; j++) {
            int f = tid + 256 * j;
            int r = f >> 4, c4 = f & 15;
            *(float4*)&Ws[r * 68 + c4 * 4] = ((const float4*)(aw + i * 4096))[f];
        }
        __syncthreads();
        float acc[4][4] = {};
#pragma unroll 8
        for (int c = 0; c < 64; c++) gemm_step(Ws, Xs, c, tx, ty, acc);

        float4 bv = *(const float4*)&ab[i * 64 + tx * 4];
        float4 sv = *(const float4*)&as_[i * 64 + tx * 4];
        float4 b2 = *(const float4*)&abb[i * 64 + tx * 4];
#pragma unroll
        for (int ii = 0; ii < 4; ii++) {
            int m = m0 + ty * 4 + ii;
            float4 mv = *(const float4*)&ms[((size_t)i * MP + m) * 64 + tx * 4];
            float ax = 1.0f / (1.0f + __expf(-((acc[ii][0] + bv.x) * sv.x + b2.x)));
            float ay = 1.0f / (1.0f + __expf(-((acc[ii][1] + bv.y) * sv.y + b2.y)));
            float az = 1.0f / (1.0f + __expf(-((acc[ii][2] + bv.z) * sv.z + b2.z)));
            float aw4 = 1.0f / (1.0f + __expf(-((acc[ii][3] + bv.w) * sv.w + b2.w)));
            fac[ii][0] += ax * mv.x;
            fac[ii][1] += ay * mv.y;
            fac[ii][2] += az * mv.z;
            fac[ii][3] += aw4 * mv.w;
        }
        __syncthreads();
    }
#pragma unroll
    for (int i = 0; i < 4; i++) {
        int m = m0 + ty * 4 + i;
        float4 o = make_float4(fac[i][0], fac[i][1], fac[i][2], fac[i][3]);
        *(float4*)&fused[(size_t)m * 64 + tx * 4] = o;
    }
}

__global__ __launch_bounds__(256) void gemm_n20_kernel(
    const float* __restrict__ X, const float* __restrict__ W,
    const float* __restrict__ b, float* __restrict__ out) {
    __shared__ float Xs[128 * 68];
    __shared__ float Ws[64 * 20];
    __shared__ float bs[20];
    const int tid = threadIdx.x;
    const int m0 = blockIdx.x * 128;
#pragma unroll
    for (int j = 0; j < 8; j++) {
        int f = tid + 256 * j;
        int r = f >> 4, c4 = f & 15;
        int m = m0 + r;
        float4 v = make_float4(0.f, 0.f, 0.f, 0.f);
        if (m < MP) v = *(const float4*)&X[(size_t)m * 64 + c4 * 4];
        *(float4*)&Xs[r * 68 + c4 * 4] = v;
    }
    for (int f = tid; f < 64 * 20; f += 256) Ws[f] = W[f];
    if (tid < 20) bs[tid] = b[tid];
    __syncthreads();
    int r = tid >> 1, half = tid & 1, n0 = half * 10;
    int m = m0 + r;
    if (m < MP) {
        float acc[10];
#pragma unroll
        for (int j = 0; j < 10; j++) acc[j] = bs[n0 + j];
#pragma unroll 8
        for (int c = 0; c < 64; c++) {
            float x = Xs[r * 68 + c];
#pragma unroll
            for (int j = 0; j < 10; j++) acc[j] += x * Ws[c * 20 + n0 + j];
        }
#pragma unroll
        for (int j = 0; j < 10; j++) out[(size_t)m * 20 + n0 + j] = acc[j];
    }
}

// ==============================================================================
extern "C" void kernel_launch(void* const* d_in, const int* in_sizes, int n_in,
                              void* d_out, int out_size) {
    const float* feats   = (const float*)d_in[0];
    const float* w1a     = (const float*)d_in[1];
    const float* s1a     = (const float*)d_in[2];
    const float* b1a     = (const float*)d_in[3];
    const float* w3      = (const float*)d_in[4];
    const float* s3      = (const float*)d_in[5];
    const float* b3      = (const float*)d_in[6];
    const float* w1b     = (const float*)d_in[7];
    const float* s1b     = (const float*)d_in[8];
    const float* b1b     = (const float*)d_in[9];
    const float* aux_w   = (const float*)d_in[10];
    const float* aux_b   = (const float*)d_in[11];
    const float* proj_w  = (const float*)d_in[12];
    const float* proj_b  = (const float*)d_in[13];
    const float* proj_s  = (const float*)d_in[14];
    const float* proj_bb = (const float*)d_in[15];
    const float* attn_w  = (const float*)d_in[16];
    const float* attn_b  = (const float*)d_in[17];
    const float* attn_s  = (const float*)d_in[18];
    const float* attn_bb = (const float*)d_in[19];
    const float* head_w  = (const float*)d_in[20];
    const float* head_b  = (const float*)d_in[21];
    const int*   nbr     = (const int*)d_in[22];
    const int*   inv     = (const int*)d_in[23];

    float* out    = (float*)d_out;
    float* fused  = out;
    float* logits = out + (size_t)MP * 64;
    float* aux    = out + (size_t)MP * 84;

    float *pV, *pms, *psx, *pvs, *pvc;
    __half *pX16, *pH16, *pB16, *pW1a, *pW1b, *pW3;
    cudaGetSymbolAddress((void**)&pV, g_V);
    cudaGetSymbolAddress((void**)&pms, g_ms);
    cudaGetSymbolAddress((void**)&psx, g_sumx);
    cudaGetSymbolAddress((void**)&pvs, g_vsum);
    cudaGetSymbolAddress((void**)&pvc, g_vcnt);
    cudaGetSymbolAddress((void**)&pX16, g_X16);
    cudaGetSymbolAddress((void**)&pH16, g_H16);
    cudaGetSymbolAddress((void**)&pB16, g_B16);
    cudaGetSymbolAddress((void**)&pW1a, g_W1a16);
    cudaGetSymbolAddress((void**)&pW1b, g_W1b16);
    cudaGetSymbolAddress((void**)&pW3, g_W316);

    cudaFuncSetAttribute(conv27_mma_kernel, cudaFuncAttributeMaxDynamicSharedMemorySize, CV_TOT);

    wprep_kernel<<<(116 * 4096 + 255) / 256, 256>>>(w1a, w1b, w3, pW1a, pW1b, pW3);
    cvt16_kernel<<<(MP * 32 + 255) / 256, 256>>>(feats, pX16);

    for (int i = 0; i < 4; i++) {
        gemm64h_kernel<<<GTC, 256>>>(pX16, pW1a + (size_t)i * 4096, s1a + i * 64, b1a + i * 64,
                                     pH16, nullptr, 2, nullptr);
        conv27_mma_kernel<<<GTC, 256, CV_TOT>>>(pH16, nbr, pW3 + (size_t)i * 27 * 4096,
                                                s3 + i * 64, b3 + i * 64, pB16);
        if (i < 3) {
            gemm64h_kernel<<<GTC, 256>>>(pB16, pW1b + (size_t)i * 4096, s1b + i * 64, b1b + i * 64,
                                         pX16, nullptr, 2, nullptr);
        } else {
            gemm64h_kernel<<<GTC, 256>>>(pB16, pW1b + (size_t)i * 4096, s1b + i * 64, b1b + i * 64,
                                         nullptr, pV, 1, feats);
        }
    }

    gemm_n20_kernel<<<938, 256>>>(pV, aux_w, aux_b, aux);

    for (int si = 0; si < 4; si++) {
        zero_kernel<<<30000, 256>>>(pvs, pvc);
        scatter_kernel<<<30000, 256>>>(pV, inv + (size_t)si * MP, pvs, pvc);
        proj_kernel<<<G64, 256>>>(pV, inv + (size_t)si * MP, pvs, pvc,
                                  proj_w + si * 4096, proj_b + si * 64,
                                  proj_s + si * 64, proj_bb + si * 64,
                                  pms + (size_t)si * MP * 64);
    }

    sumx_kernel<<<7500, 256>>>(pms, psx);
    attn_kernel<<<G64, 256>>>(psx, pms, attn_w, attn_b, attn_s, attn_bb, fused);
    gemm_n20_kernel<<<938, 256>>>(fused, head_w, head_b, logits);
}

// round 5
// speedup vs baseline: 3.8767x; 1.1622x over previous
#include <cuda_runtime.h>
#include <cuda_fp16.h>
#include <math.h>
#include <stdint.h>

#define MP 120000
#define GTC 938     // ceil(MP / 128)

// ---------------- scratch (static device globals; no runtime allocs) ----------
__device__ float  g_V[MP * 64];
__device__ __half g_X16[MP * 64];
__device__ __half g_H16[MP * 64];
__device__ __half g_B16[MP * 64];
__device__ __half g_W1a16[4 * 4096];
__device__ __half g_W1b16[4 * 4096];
__device__ __half g_W316[4 * 27 * 4096];
__device__ __half g_Wp16[4 * 4096];
__device__ __half g_Wa16[4 * 4096];
__device__ float  g_ms[4 * MP * 64];
__device__ float  g_vsum4[4 * MP * 64];
__device__ float  g_vcnt4[4 * MP];

__device__ __forceinline__ float lrelu(float x, float a) { return x > 0.f ? x : a * x; }

__device__ __forceinline__ uint32_t smem_u32(const void* p) {
    uint32_t a;
    asm("{ .reg .u64 t; cvta.to.shared.u64 t, %1; cvt.u32.u64 %0, t; }" : "=r"(a) : "l"(p));
    return a;
}

__device__ __forceinline__ void ldm4(uint32_t r[4], uint32_t addr) {
    asm volatile("ldmatrix.sync.aligned.m8n8.x4.shared.b16 {%0,%1,%2,%3}, [%4];"
                 : "=r"(r[0]), "=r"(r[1]), "=r"(r[2]), "=r"(r[3]) : "r"(addr));
}

__device__ __forceinline__ void mma16816(float c[4], const uint32_t a[4],
                                         uint32_t b0, uint32_t b1) {
    asm volatile(
        "mma.sync.aligned.m16n8k16.row.col.f32.f16.f16.f32 "
        "{%0,%1,%2,%3},{%4,%5,%6,%7},{%8,%9},{%0,%1,%2,%3};"
        : "+f"(c[0]), "+f"(c[1]), "+f"(c[2]), "+f"(c[3])
        : "r"(a[0]), "r"(a[1]), "r"(a[2]), "r"(a[3]), "r"(b0), "r"(b1));
}

#define CP16(dst, src) \
    asm volatile("cp.async.cg.shared.global [%0], [%1], 16;" :: "r"(dst), "l"(src))
#define CP_COMMIT() asm volatile("cp.async.commit_group;" ::: "memory")
#define CP_WAIT(n)  asm volatile("cp.async.wait_group %0;" :: "n"(n) : "memory")
#define STS_ZERO(dst) do { uint32_t _z = 0; \
    asm volatile("st.shared.v4.b32 [%0], {%1,%1,%1,%1};" :: "r"(dst), "r"(_z)); } while (0)

// ========== common MMA core: A(128x64) x W(64x64)^T, 8 warps, acc per warp =====
__device__ __forceinline__ void mma_tile_64(uint32_t a_s, uint32_t w_s,
                                            int lane, int wm, int wn,
                                            float acc[2][4][4]) {
#pragma unroll
    for (int kb = 0; kb < 4; kb++) {
        uint32_t a[2][4], wh[2][4];
#pragma unroll
        for (int mt = 0; mt < 2; mt++) {
            int r = wm + mt * 16 + (lane & 15);
            int lc = kb * 2 + (lane >> 4);
            ldm4(a[mt], a_s + r * 128 + ((lc ^ (r & 7)) << 4));
        }
#pragma unroll
        for (int np = 0; np < 2; np++) {
            int r = wn + np * 16 + (lane & 7) + ((lane & 16) ? 8 : 0);
            int lc = kb * 2 + ((lane >> 3) & 1);
            ldm4(wh[np], w_s + r * 128 + ((lc ^ (r & 7)) << 4));
        }
#pragma unroll
        for (int mt = 0; mt < 2; mt++)
#pragma unroll
            for (int nt = 0; nt < 4; nt++) {
                int np = nt >> 1, q = (nt & 1) * 2;
                mma16816(acc[mt][nt], a[mt], wh[np][q], wh[np][q + 1]);
            }
    }
}

// =================== weight prep: transpose + fp16 ===========================
// 124 mats: [0,4) w1a, [4,8) w1b, [8,116) w3, [116,120) proj_w, [120,124) attn_w
__global__ void wprep_kernel(const float* __restrict__ w1a, const float* __restrict__ w1b,
                             const float* __restrict__ w3, const float* __restrict__ wp,
                             const float* __restrict__ wa,
                             __half* __restrict__ o1a, __half* __restrict__ o1b,
                             __half* __restrict__ o3, __half* __restrict__ op,
                             __half* __restrict__ oa) {
    int g = blockIdx.x * 256 + threadIdx.x;
    if (g >= 124 * 4096) return;
    int t = g >> 12;
    int rc = g & 4095;
    int d = rc >> 6, c = rc & 63;
    if (t < 4)
        o1a[(size_t)t * 4096 + d * 64 + c] = __float2half_rn(w1a[(size_t)t * 4096 + c * 64 + d]);
    else if (t < 8)
        o1b[(size_t)(t - 4) * 4096 + d * 64 + c] = __float2half_rn(w1b[(size_t)(t - 4) * 4096 + c * 64 + d]);
    else if (t < 116)
        o3[(size_t)(t - 8) * 4096 + d * 64 + c] = __float2half_rn(w3[(size_t)(t - 8) * 4096 + c * 64 + d]);
    else if (t < 120)
        op[(size_t)(t - 116) * 4096 + d * 64 + c] = __float2half_rn(wp[(size_t)(t - 116) * 4096 + c * 64 + d]);
    else
        oa[(size_t)(t - 120) * 4096 + d * 64 + c] = __float2half_rn(wa[(size_t)(t - 120) * 4096 + c * 64 + d]);
}

__global__ void cvt16_kernel(const float* __restrict__ x, __half* __restrict__ o) {
    int g = blockIdx.x * 256 + threadIdx.x;
    if (g >= MP * 32) return;
    float2 v = ((const float2*)x)[g];
    ((__half2*)o)[g] = __float22half2_rn(v);
}

// ================= tensorized 64x64 GEMM (M-tile 128, 8 warps) ================
__global__ __launch_bounds__(256) void gemm64h_kernel(
    const __half* __restrict__ X, const __half* __restrict__ W,
    const float* __restrict__ s, const float* __restrict__ b,
    __half* __restrict__ outh, float* __restrict__ outf,
    int mode, const float* __restrict__ feats) {
    __shared__ __align__(16) char smA[16384];
    __shared__ __align__(16) char smW[8192];
    const uint32_t a_s = smem_u32(smA);
    const uint32_t w_s = smem_u32(smW);
    const int tid = threadIdx.x;
    const int lane = tid & 31, wid = tid >> 5;
    const int m0 = blockIdx.x * 128;

#pragma unroll
    for (int j = 0; j < 4; j++) {
        int f = tid + j * 256;
        int r = f >> 3, c = f & 7;
        uint32_t dst = a_s + r * 128 + ((c ^ (r & 7)) << 4);
        if (m0 + r < MP) CP16(dst, X + (size_t)(m0 + r) * 64 + c * 8);
        else STS_ZERO(dst);
    }
#pragma unroll
    for (int j = 0; j < 2; j++) {
        int f = tid + j * 256;
        int r = f >> 3, c = f & 7;
        CP16(w_s + r * 128 + ((c ^ (r & 7)) << 4), W + (size_t)r * 64 + c * 8);
    }
    CP_COMMIT();
    CP_WAIT(0);
    __syncthreads();

    const int wm = (wid >> 1) * 32;
    const int wn = (wid & 1) * 32;
    float acc[2][4][4] = {};
    mma_tile_64(a_s, w_s, lane, wm, wn, acc);

    const int qr = lane >> 2, qc = lane & 3;
#pragma unroll
    for (int mt = 0; mt < 2; mt++) {
#pragma unroll
        for (int nt = 0; nt < 4; nt++) {
            int col = wn + nt * 8 + qc * 2;
            float2 s2 = *(const float2*)&s[col];
            float2 b2 = *(const float2*)&b[col];
            int r0 = m0 + wm + mt * 16 + qr;
            int r1 = r0 + 8;
            float v0 = lrelu(acc[mt][nt][0] * s2.x + b2.x, 0.01f);
            float v1 = lrelu(acc[mt][nt][1] * s2.y + b2.y, 0.01f);
            float v2 = lrelu(acc[mt][nt][2] * s2.x + b2.x, 0.01f);
            float v3 = lrelu(acc[mt][nt][3] * s2.y + b2.y, 0.01f);
            if (mode == 2) {
                if (r0 < MP) *(__half2*)&outh[(size_t)r0 * 64 + col] =
                    __float22half2_rn(make_float2(v0, v1));
                if (r1 < MP) *(__half2*)&outh[(size_t)r1 * 64 + col] =
                    __float22half2_rn(make_float2(v2, v3));
            } else {
                if (r0 < MP) {
                    float2 fr = *(const float2*)&feats[(size_t)r0 * 64 + col];
                    *(float2*)&outf[(size_t)r0 * 64 + col] =
                        make_float2(lrelu(v0 + fr.x, 0.1f), lrelu(v1 + fr.y, 0.1f));
                }
                if (r1 < MP) {
                    float2 fr = *(const float2*)&feats[(size_t)r1 * 64 + col];
                    *(float2*)&outf[(size_t)r1 * 64 + col] =
                        make_float2(lrelu(v2 + fr.x, 0.1f), lrelu(v3 + fr.y, 0.1f));
                }
            }
        }
    }
}

// =========== mma.sync fp16 27-tap submanifold conv (3-stage pipeline) =========
// smem: nidxT[27][128] int (13824 -> 14336) | A 16KB x3 | W 8KB x3 = 88064 bytes
#define CV_NIDX 0
#define CV_A(st) (14336 + (st) * 16384)
#define CV_W(st) (63488 + (st) * 8192)
#define CV_TOT   88064

__device__ __forceinline__ void cv_fill(uint32_t sb, int stage, int k,
                                        const int* __restrict__ nidxT,
                                        const __half* __restrict__ H,
                                        const __half* __restrict__ Wh, int tid) {
    uint32_t a_s = sb + CV_A(stage);
    uint32_t h_s = sb + CV_W(stage);
#pragma unroll
    for (int j = 0; j < 4; j++) {
        int t = tid + j * 256;
        int r = t >> 3, c = t & 7;
        int row = nidxT[k * 128 + r];
        uint32_t dst = a_s + r * 128 + ((c ^ (r & 7)) << 4);
        if (row >= 0) CP16(dst, H + (size_t)row * 64 + c * 8);
        else STS_ZERO(dst);
    }
    const __half* WhK = Wh + (size_t)k * 4096;
#pragma unroll
    for (int j = 0; j < 2; j++) {
        int t = tid + j * 256;
        int r = t >> 3, c = t & 7;
        CP16(h_s + r * 128 + ((c ^ (r & 7)) << 4), WhK + r * 64 + c * 8);
    }
}

__global__ __launch_bounds__(256, 2) void conv27_mma_kernel(
    const __half* __restrict__ H, const int* __restrict__ nbr,
    const __half* __restrict__ Wh,
    const float* __restrict__ s, const float* __restrict__ b,
    __half* __restrict__ out) {
    extern __shared__ char smc[];
    const uint32_t sb = smem_u32(smc);
    const int tid = threadIdx.x;
    const int lane = tid & 31, wid = tid >> 5;
    const int m0 = blockIdx.x * 128;
    int* nidxT = (int*)smc;
    for (int t = tid; t < 27 * 128; t += 256) {
        int k = t >> 7, r = t & 127;
        int m = m0 + r;
        nidxT[t] = (m < MP) ? nbr[(size_t)m * 27 + k] : -1;
    }
    __syncthreads();

    cv_fill(sb, 0, 0, nidxT, H, Wh, tid);
    CP_COMMIT();
    cv_fill(sb, 1, 1, nidxT, H, Wh, tid);
    CP_COMMIT();

    const int wm = (wid >> 1) * 32;
    const int wn = (wid & 1) * 32;
    float acc[2][4][4] = {};
    int stage = 0;

    for (int k = 0; k < 27; k++) {
        if (k < 26) CP_WAIT(1);
        else        CP_WAIT(0);
        __syncthreads();
        if (k < 25) {
            int ns = stage + 2;
            if (ns >= 3) ns -= 3;
            cv_fill(sb, ns, k + 2, nidxT, H, Wh, tid);
            CP_COMMIT();
        }
        mma_tile_64(sb + CV_A(stage), sb + CV_W(stage), lane, wm, wn, acc);
        if (++stage == 3) stage = 0;
    }

    const int qr = lane >> 2, qc = lane & 3;
#pragma unroll
    for (int mt = 0; mt < 2; mt++) {
#pragma unroll
        for (int nt = 0; nt < 4; nt++) {
            int col = wn + nt * 8 + qc * 2;
            float2 s2 = *(const float2*)&s[col];
            float2 b2 = *(const float2*)&b[col];
            int r0 = m0 + wm + mt * 16 + qr;
            int r1 = r0 + 8;
            float v0 = lrelu(acc[mt][nt][0] * s2.x + b2.x, 0.01f);
            float v1 = lrelu(acc[mt][nt][1] * s2.y + b2.y, 0.01f);
            float v2 = lrelu(acc[mt][nt][2] * s2.x + b2.x, 0.01f);
            float v3 = lrelu(acc[mt][nt][3] * s2.y + b2.y, 0.01f);
            if (r0 < MP) *(__half2*)&out[(size_t)r0 * 64 + col] =
                __float22half2_rn(make_float2(v0, v1));
            if (r1 < MP) *(__half2*)&out[(size_t)r1 * 64 + col] =
                __float22half2_rn(make_float2(v2, v3));
        }
    }
}

// =================== batched scatter-mean over all 4 scales ===================
__global__ void zero_all_kernel(float* __restrict__ vsum4, float* __restrict__ vcnt4) {
    int gid = blockIdx.x * 256 + threadIdx.x;
    if (gid < 4 * MP * 64) vsum4[gid] = 0.f;
    if (gid < 4 * MP) vcnt4[gid] = 0.f;
}

__global__ void scatter_all_kernel(const float* __restrict__ V, const int* __restrict__ inv,
                                   float* __restrict__ vsum4, float* __restrict__ vcnt4) {
    int gid = blockIdx.x * 256 + threadIdx.x;
    if (gid >= 4 * MP * 64) return;
    int si = gid / (MP * 64);
    int rem = gid - si * (MP * 64);
    int m = rem >> 6, c = rem & 63;
    int sg = inv[si * MP + m];
    atomicAdd(&vsum4[(size_t)si * MP * 64 + sg * 64 + c], V[rem]);
    if (c == 0) atomicAdd(&vcnt4[si * MP + sg], 1.0f);
}

// ============ tensorized proj: Os=(V-mean)*V (fp16) @ proj_w, grid (GTC,4) ====
__global__ __launch_bounds__(256) void proj_mma_kernel(
    const float* __restrict__ V, const int* __restrict__ inv,
    const float* __restrict__ vsum4, const float* __restrict__ vcnt4,
    const __half* __restrict__ Wp, const float* __restrict__ pb,
    const float* __restrict__ ps, const float* __restrict__ pbb,
    float* __restrict__ ms) {
    __shared__ __align__(16) char smA[16384];
    __shared__ __align__(16) char smW[8192];
    const uint32_t a_s = smem_u32(smA);
    const uint32_t w_s = smem_u32(smW);
    const int tid = threadIdx.x;
    const int lane = tid & 31, wid = tid >> 5;
    const int m0 = blockIdx.x * 128;
    const int si = blockIdx.y;
    const int* seg = inv + (size_t)si * MP;
    const float* vsum = vsum4 + (size_t)si * MP * 64;
    const float* vcnt = vcnt4 + (size_t)si * MP;
    float* msO = ms + (size_t)si * MP * 64;

#pragma unroll
    for (int j = 0; j < 2; j++) {
        int f = tid + j * 256;
        int r = f >> 3, c = f & 7;
        CP16(w_s + r * 128 + ((c ^ (r & 7)) << 4),
             Wp + (size_t)si * 4096 + r * 64 + c * 8);
    }
    CP_COMMIT();
#pragma unroll
    for (int j = 0; j < 4; j++) {
        int f = tid + j * 256;
        int r = f >> 3, c = f & 7;
        uint32_t dst = a_s + r * 128 + ((c ^ (r & 7)) << 4);
        int m = m0 + r;
        if (m < MP) {
            int sg = seg[m];
            float rc = 1.0f / fmaxf(vcnt[sg], 1.0f);
            float4 v0 = *(const float4*)&V[(size_t)m * 64 + c * 8];
            float4 v1 = *(const float4*)&V[(size_t)m * 64 + c * 8 + 4];
            float4 u0 = *(const float4*)&vsum[(size_t)sg * 64 + c * 8];
            float4 u1 = *(const float4*)&vsum[(size_t)sg * 64 + c * 8 + 4];
            __half2 h0 = __float22half2_rn(make_float2((v0.x - u0.x * rc) * v0.x,
                                                       (v0.y - u0.y * rc) * v0.y));
            __half2 h1 = __float22half2_rn(make_float2((v0.z - u0.z * rc) * v0.z,
                                                       (v0.w - u0.w * rc) * v0.w));
            __half2 h2 = __float22half2_rn(make_float2((v1.x - u1.x * rc) * v1.x,
                                                       (v1.y - u1.y * rc) * v1.y));
            __half2 h3 = __float22half2_rn(make_float2((v1.z - u1.z * rc) * v1.z,
                                                       (v1.w - u1.w * rc) * v1.w));
            uint32_t q0 = *(uint32_t*)&h0, q1 = *(uint32_t*)&h1;
            uint32_t q2 = *(uint32_t*)&h2, q3 = *(uint32_t*)&h3;
            asm volatile("st.shared.v4.b32 [%0], {%1,%2,%3,%4};"
                         :: "r"(dst), "r"(q0), "r"(q1), "r"(q2), "r"(q3));
        } else {
            STS_ZERO(dst);
        }
    }
    CP_WAIT(0);
    __syncthreads();

    const int wm = (wid >> 1) * 32;
    const int wn = (wid & 1) * 32;
    float acc[2][4][4] = {};
    mma_tile_64(a_s, w_s, lane, wm, wn, acc);

    const int qr = lane >> 2, qc = lane & 3;
#pragma unroll
    for (int mt = 0; mt < 2; mt++) {
#pragma unroll
        for (int nt = 0; nt < 4; nt++) {
            int col = wn + nt * 8 + qc * 2;
            float2 bv = *(const float2*)&pb[si * 64 + col];
            float2 sv = *(const float2*)&ps[si * 64 + col];
            float2 b2 = *(const float2*)&pbb[si * 64 + col];
            int r0 = m0 + wm + mt * 16 + qr;
            int r1 = r0 + 8;
            if (r0 < MP) *(float2*)&msO[(size_t)r0 * 64 + col] = make_float2(
                lrelu((acc[mt][nt][0] + bv.x) * sv.x + b2.x, 0.01f),
                lrelu((acc[mt][nt][1] + bv.y) * sv.y + b2.y, 0.01f));
            if (r1 < MP) *(float2*)&msO[(size_t)r1 * 64 + col] = make_float2(
                lrelu((acc[mt][nt][2] + bv.x) * sv.x + b2.x, 0.01f),
                lrelu((acc[mt][nt][3] + bv.y) * sv.y + b2.y, 0.01f));
        }
    }
}

// ===== tensorized attn: sumx built in-kernel (fp16), 4 GEMMs, fused output ====
__global__ __launch_bounds__(256) void attn_mma_kernel(
    const float* __restrict__ ms, const __half* __restrict__ Wa,
    const float* __restrict__ ab, const float* __restrict__ as_,
    const float* __restrict__ abb, float* __restrict__ fused) {
    __shared__ __align__(16) char smA[16384];
    __shared__ __align__(16) char smW[8192];
    const uint32_t a_s = smem_u32(smA);
    const uint32_t w_s = smem_u32(smW);
    const int tid = threadIdx.x;
    const int lane = tid & 31, wid = tid >> 5;
    const int m0 = blockIdx.x * 128;

    // build sumx tile in fp16
#pragma unroll
    for (int j = 0; j < 4; j++) {
        int f = tid + j * 256;
        int r = f >> 3, c = f & 7;
        uint32_t dst = a_s + r * 128 + ((c ^ (r & 7)) << 4);
        int m = m0 + r;
        if (m < MP) {
            float sx[8] = {};
#pragma unroll
            for (int i = 0; i < 4; i++) {
                float4 v0 = *(const float4*)&ms[((size_t)i * MP + m) * 64 + c * 8];
                float4 v1 = *(const float4*)&ms[((size_t)i * MP + m) * 64 + c * 8 + 4];
                sx[0] += v0.x; sx[1] += v0.y; sx[2] += v0.z; sx[3] += v0.w;
                sx[4] += v1.x; sx[5] += v1.y; sx[6] += v1.z; sx[7] += v1.w;
            }
            __half2 h0 = __float22half2_rn(make_float2(sx[0], sx[1]));
            __half2 h1 = __float22half2_rn(make_float2(sx[2], sx[3]));
            __half2 h2 = __float22half2_rn(make_float2(sx[4], sx[5]));
            __half2 h3 = __float22half2_rn(make_float2(sx[6], sx[7]));
            uint32_t q0 = *(uint32_t*)&h0, q1 = *(uint32_t*)&h1;
            uint32_t q2 = *(uint32_t*)&h2, q3 = *(uint32_t*)&h3;
            asm volatile("st.shared.v4.b32 [%0], {%1,%2,%3,%4};"
                         :: "r"(dst), "r"(q0), "r"(q1), "r"(q2), "r"(q3));
        } else {
            STS_ZERO(dst);
        }
    }

    const int wm = (wid >> 1) * 32;
    const int wn = (wid & 1) * 32;
    const int qr = lane >> 2, qc = lane & 3;
    float fac[2][4][4] = {};

    for (int i = 0; i < 4; i++) {
        __syncthreads();   // previous readers of smW done (and iter0: smA stores visible)
#pragma unroll
        for (int j = 0; j < 2; j++) {
            int f = tid + j * 256;
            int r = f >> 3, c = f & 7;
            CP16(w_s + r * 128 + ((c ^ (r & 7)) << 4),
                 Wa + (size_t)i * 4096 + r * 64 + c * 8);
        }
        CP_COMMIT();
        CP_WAIT(0);
        __syncthreads();

        float acc[2][4][4] = {};
        mma_tile_64(a_s, w_s, lane, wm, wn, acc);

#pragma unroll
        for (int mt = 0; mt < 2; mt++) {
#pragma unroll
            for (int nt = 0; nt < 4; nt++) {
                int col = wn + nt * 8 + qc * 2;
                float2 bv = *(const float2*)&ab[i * 64 + col];
                float2 sv = *(const float2*)&as_[i * 64 + col];
                float2 b2 = *(const float2*)&abb[i * 64 + col];
                int r0 = m0 + wm + mt * 16 + qr;
                int r1 = r0 + 8;
                if (r0 < MP) {
                    float2 mv = *(const float2*)&ms[((size_t)i * MP + r0) * 64 + col];
                    float a0 = 1.0f / (1.0f + __expf(-((acc[mt][nt][0] + bv.x) * sv.x + b2.x)));
                    float a1 = 1.0f / (1.0f + __expf(-((acc[mt][nt][1] + bv.y) * sv.y + b2.y)));
                    fac[mt][nt][0] += a0 * mv.x;
                    fac[mt][nt][1] += a1 * mv.y;
                }
                if (r1 < MP) {
                    float2 mv = *(const float2*)&ms[((size_t)i * MP + r1) * 64 + col];
                    float a2 = 1.0f / (1.0f + __expf(-((acc[mt][nt][2] + bv.x) * sv.x + b2.x)));
                    float a3 = 1.0f / (1.0f + __expf(-((acc[mt][nt][3] + bv.y) * sv.y + b2.y)));
                    fac[mt][nt][2] += a2 * mv.x;
                    fac[mt][nt][3] += a3 * mv.y;
                }
            }
        }
    }

#pragma unroll
    for (int mt = 0; mt < 2; mt++) {
#pragma unroll
        for (int nt = 0; nt < 4; nt++) {
            int col = wn + nt * 8 + qc * 2;
            int r0 = m0 + wm + mt * 16 + qr;
            int r1 = r0 + 8;
            if (r0 < MP) *(float2*)&fused[(size_t)r0 * 64 + col] =
                make_float2(fac[mt][nt][0], fac[mt][nt][1]);
            if (r1 < MP) *(float2*)&fused[(size_t)r1 * 64 + col] =
                make_float2(fac[mt][nt][2], fac[mt][nt][3]);
        }
    }
}

// ================================ N=20 heads ==================================
__global__ __launch_bounds__(256) void gemm_n20_kernel(
    const float* __restrict__ X, const float* __restrict__ W,
    const float* __restrict__ b, float* __restrict__ out) {
    __shared__ float Xs[128 * 68];
    __shared__ float Ws[64 * 20];
    __shared__ float bs[20];
    const int tid = threadIdx.x;
    const int m0 = blockIdx.x * 128;
#pragma unroll
    for (int j = 0; j < 8; j++) {
        int f = tid + 256 * j;
        int r = f >> 4, c4 = f & 15;
        int m = m0 + r;
        float4 v = make_float4(0.f, 0.f, 0.f, 0.f);
        if (m < MP) v = *(const float4*)&X[(size_t)m * 64 + c4 * 4];
        *(float4*)&Xs[r * 68 + c4 * 4] = v;
    }
    for (int f = tid; f < 64 * 20; f += 256) Ws[f] = W[f];
    if (tid < 20) bs[tid] = b[tid];
    __syncthreads();
    int r = tid >> 1, half = tid & 1, n0 = half * 10;
    int m = m0 + r;
    if (m < MP) {
        float acc[10];
#pragma unroll
        for (int j = 0; j < 10; j++) acc[j] = bs[n0 + j];
#pragma unroll 8
        for (int c = 0; c < 64; c++) {
            float x = Xs[r * 68 + c];
#pragma unroll
            for (int j = 0; j < 10; j++) acc[j] += x * Ws[c * 20 + n0 + j];
        }
#pragma unroll
        for (int j = 0; j < 10; j++) out[(size_t)m * 20 + n0 + j] = acc[j];
    }
}

// ==============================================================================
extern "C" void kernel_launch(void* const* d_in, const int* in_sizes, int n_in,
                              void* d_out, int out_size) {
    const float* feats   = (const float*)d_in[0];
    const float* w1a     = (const float*)d_in[1];
    const float* s1a     = (const float*)d_in[2];
    const float* b1a     = (const float*)d_in[3];
    const float* w3      = (const float*)d_in[4];
    const float* s3      = (const float*)d_in[5];
    const float* b3      = (const float*)d_in[6];
    const float* w1b     = (const float*)d_in[7];
    const float* s1b     = (const float*)d_in[8];
    const float* b1b     = (const float*)d_in[9];
    const float* aux_w   = (const float*)d_in[10];
    const float* aux_b   = (const float*)d_in[11];
    const float* proj_w  = (const float*)d_in[12];
    const float* proj_b  = (const float*)d_in[13];
    const float* proj_s  = (const float*)d_in[14];
    const float* proj_bb = (const float*)d_in[15];
    const float* attn_w  = (const float*)d_in[16];
    const float* attn_b  = (const float*)d_in[17];
    const float* attn_s  = (const float*)d_in[18];
    const float* attn_bb = (const float*)d_in[19];
    const float* head_w  = (const float*)d_in[20];
    const float* head_b  = (const float*)d_in[21];
    const int*   nbr     = (const int*)d_in[22];
    const int*   inv     = (const int*)d_in[23];

    float* out    = (float*)d_out;
    float* fused  = out;
    float* logits = out + (size_t)MP * 64;
    float* aux    = out + (size_t)MP * 84;

    float *pV, *pms, *pvs, *pvc;
    __half *pX16, *pH16, *pB16, *pW1a, *pW1b, *pW3, *pWp, *pWa;
    cudaGetSymbolAddress((void**)&pV, g_V);
    cudaGetSymbolAddress((void**)&pms, g_ms);
    cudaGetSymbolAddress((void**)&pvs, g_vsum4);
    cudaGetSymbolAddress((void**)&pvc, g_vcnt4);
    cudaGetSymbolAddress((void**)&pX16, g_X16);
    cudaGetSymbolAddress((void**)&pH16, g_H16);
    cudaGetSymbolAddress((void**)&pB16, g_B16);
    cudaGetSymbolAddress((void**)&pW1a, g_W1a16);
    cudaGetSymbolAddress((void**)&pW1b, g_W1b16);
    cudaGetSymbolAddress((void**)&pW3, g_W316);
    cudaGetSymbolAddress((void**)&pWp, g_Wp16);
    cudaGetSymbolAddress((void**)&pWa, g_Wa16);

    cudaFuncSetAttribute(conv27_mma_kernel, cudaFuncAttributeMaxDynamicSharedMemorySize, CV_TOT);

    wprep_kernel<<<(124 * 4096 + 255) / 256, 256>>>(w1a, w1b, w3, proj_w, attn_w,
                                                    pW1a, pW1b, pW3, pWp, pWa);
    cvt16_kernel<<<(MP * 32 + 255) / 256, 256>>>(feats, pX16);

    for (int i = 0; i < 4; i++) {
        gemm64h_kernel<<<GTC, 256>>>(pX16, pW1a + (size_t)i * 4096, s1a + i * 64, b1a + i * 64,
                                     pH16, nullptr, 2, nullptr);
        conv27_mma_kernel<<<GTC, 256, CV_TOT>>>(pH16, nbr, pW3 + (size_t)i * 27 * 4096,
                                                s3 + i * 64, b3 + i * 64, pB16);
        if (i < 3) {
            gemm64h_kernel<<<GTC, 256>>>(pB16, pW1b + (size_t)i * 4096, s1b + i * 64, b1b + i * 64,
                                         pX16, nullptr, 2, nullptr);
        } else {
            gemm64h_kernel<<<GTC, 256>>>(pB16, pW1b + (size_t)i * 4096, s1b + i * 64, b1b + i * 64,
                                         nullptr, pV, 1, feats);
        }
    }

    gemm_n20_kernel<<<938, 256>>>(pV, aux_w, aux_b, aux);

    zero_all_kernel<<<120000, 256>>>(pvs, pvc);
    scatter_all_kernel<<<120000, 256>>>(pV, inv, pvs, pvc);
    {
        dim3 grid(GTC, 4);
        proj_mma_kernel<<<grid, 256>>>(pV, inv, pvs, pvc, pWp,
                                       proj_b, proj_s, proj_bb, pms);
    }
    attn_mma_kernel<<<GTC, 256>>>(pms, pWa, attn_b, attn_s, attn_bb, fused);
    gemm_n20_kernel<<<938, 256>>>(fused, head_w, head_b, logits);
}